// round 14
// baseline (speedup 1.0000x reference)
#include <cuda_runtime.h>
#include <cuda_fp16.h>
#include <math_constants.h>
#include <math.h>
#include <cstdint>

#define DIMN 2048
#define BB 2
#define SS 2048
#define HH 16
#define HDD 128
#define MTOT (BB*SS)   // 4096

#define LO_SCALE 2048.0f
#define LO_INV (1.0f / 2048.0f)

// ---------------------------------------------------------------------------
// Scratch (alloc-free rule: __device__ globals). All "lo" arrays pre-scaled
// by LO_SCALE for fp16-accumulator mma.
// ---------------------------------------------------------------------------
__device__ __half g_xh[(size_t)MTOT * DIMN];
__device__ __half g_xl[(size_t)MTOT * DIMN];
__device__ __half g_ath[(size_t)MTOT * DIMN];
__device__ __half g_atl[(size_t)MTOT * DIMN];
__device__ __half g_wth[4][(size_t)DIMN * DIMN];   // W^T hi, [N][K]
__device__ __half g_qh[(size_t)MTOT * DIMN];
__device__ __half g_ql[(size_t)MTOT * DIMN];
__device__ __half g_kh[(size_t)MTOT * DIMN];
__device__ __half g_vh[(size_t)MTOT * DIMN];
__device__ float2 g_rope[(size_t)SS * 64];         // (cos, sin) per (s, dp)

// ---------------------------------------------------------------------------
// PTX helpers (generic sm_80+ features only)
// ---------------------------------------------------------------------------
__device__ __forceinline__ void cp_async16_s(uint32_t s, const void* g) {
    asm volatile("cp.async.cg.shared.global [%0], [%1], 16;\n" :: "r"(s), "l"(g));
}
#define CP_COMMIT() asm volatile("cp.async.commit_group;\n")

__device__ __forceinline__ uint32_t smem_u32(const void* p) {
    uint32_t a;
    asm("{ .reg .u64 t; cvta.to.shared.u64 t, %1; cvt.u32.u64 %0, t; }"
        : "=r"(a) : "l"(p));
    return a;
}

__device__ __forceinline__ void ldsm_x4(uint32_t addr, uint32_t* r) {
    asm volatile("ldmatrix.sync.aligned.m8n8.x4.shared.b16 {%0,%1,%2,%3}, [%4];"
                 : "=r"(r[0]), "=r"(r[1]), "=r"(r[2]), "=r"(r[3]) : "r"(addr));
}
__device__ __forceinline__ void ldsm_x4_t(uint32_t addr, uint32_t* r) {
    asm volatile("ldmatrix.sync.aligned.m8n8.x4.trans.shared.b16 {%0,%1,%2,%3}, [%4];"
                 : "=r"(r[0]), "=r"(r[1]), "=r"(r[2]), "=r"(r[3]) : "r"(addr));
}

// fp32-accumulator mma (hi terms)
__device__ __forceinline__ void mma_f16(float* d, const uint32_t* a,
                                        uint32_t b0, uint32_t b1) {
    asm volatile(
        "mma.sync.aligned.m16n8k16.row.col.f32.f16.f16.f32 "
        "{%0,%1,%2,%3}, {%4,%5,%6,%7}, {%8,%9}, {%0,%1,%2,%3};"
        : "+f"(d[0]), "+f"(d[1]), "+f"(d[2]), "+f"(d[3])
        : "r"(a[0]), "r"(a[1]), "r"(a[2]), "r"(a[3]), "r"(b0), "r"(b1));
}

// fp16-accumulator mma (lo terms, scaled by LO_SCALE)
__device__ __forceinline__ void mma_f16h(uint32_t* d, const uint32_t* a,
                                         uint32_t b0, uint32_t b1) {
    asm volatile(
        "mma.sync.aligned.m16n8k16.row.col.f16.f16.f16.f16 "
        "{%0,%1}, {%2,%3,%4,%5}, {%6,%7}, {%0,%1};"
        : "+r"(d[0]), "+r"(d[1])
        : "r"(a[0]), "r"(a[1]), "r"(a[2]), "r"(a[3]), "r"(b0), "r"(b1));
}

// flush a 2-reg fp16 accumulator pair into 4 fp32 accumulators (unscale)
__device__ __forceinline__ void flush_lo(float* acc, const uint32_t* dlo) {
    float2 p0 = __half22float2(*(const __half2*)&dlo[0]);
    float2 p1 = __half22float2(*(const __half2*)&dlo[1]);
    acc[0] += p0.x * LO_INV; acc[1] += p0.y * LO_INV;
    acc[2] += p1.x * LO_INV; acc[3] += p1.y * LO_INV;
}

__device__ __forceinline__ void split_store(__half* h, __half* l,
                                            size_t off, float v0, float v1) {
    __half h0 = __float2half(v0), h1 = __float2half(v1);
    *(__half2*)(h + off) = __half2(h0, h1);
    *(__half2*)(l + off) = __half2(
        __float2half((v0 - __half2float(h0)) * LO_SCALE),
        __float2half((v1 - __half2float(h1)) * LO_SCALE));
}

// ---------------------------------------------------------------------------
// Prep: split fp32 rows into fp16 hi + scaled lo
// ---------------------------------------------------------------------------
__global__ void split_rows(const float* __restrict__ in,
                           __half* __restrict__ h,
                           __half* __restrict__ l) {
    size_t i = ((size_t)blockIdx.x * 256 + threadIdx.x) * 4;
    float4 v = *(const float4*)(in + i);
    split_store(h, l, i,     v.x, v.y);
    split_store(h, l, i + 2, v.z, v.w);
}

// ---------------------------------------------------------------------------
// Prep: transpose all 4 weights (blockIdx.z selects) -> W^T fp16 hi
// ---------------------------------------------------------------------------
__global__ void split_transpose_all(const float* __restrict__ W0,
                                    const float* __restrict__ W1,
                                    const float* __restrict__ W2,
                                    const float* __restrict__ W3,
                                    __half* __restrict__ th) {
    __shared__ float ts[32][33];
    const float* W = (blockIdx.z == 0) ? W0 : (blockIdx.z == 1) ? W1
                   : (blockIdx.z == 2) ? W2 : W3;
    const size_t mo = (size_t)blockIdx.z * DIMN * DIMN;
    const int bx = blockIdx.x * 32, by = blockIdx.y * 32;
    const int tx = threadIdx.x, ty = threadIdx.y;   // 32 x 8
    #pragma unroll
    for (int j = 0; j < 4; j++)
        ts[ty + 8 * j][tx] = W[(size_t)(by + ty + 8 * j) * DIMN + bx + tx];
    __syncthreads();
    #pragma unroll
    for (int j = 0; j < 4; j++) {
        float v = ts[tx][ty + 8 * j];
        th[mo + (size_t)(bx + ty + 8 * j) * DIMN + by + tx] = __float2half(v);
    }
}

// ---------------------------------------------------------------------------
// Prep: RoPE cos/sin table  g_rope[s][dp]
// ---------------------------------------------------------------------------
__global__ void rope_table() {
    int idx = blockIdx.x * 256 + threadIdx.x;    // 0 .. SS*64-1
    int s = idx >> 6, dp = idx & 63;
    float inv = powf(10000.0f, -(float)dp * (1.0f / 64.0f));
    float sn, cs;
    sincosf((float)s * inv, &sn, &cs);
    g_rope[idx] = make_float2(cs, sn);
}

// ---------------------------------------------------------------------------
// fp16 2-term split GEMM: C = Ah@Bh^T (f32 accum) + Al@Bh^T (f16 accum,
// scaled). Block tile 128x128, BK=32, 512 threads (16 warps, warp 32x32),
// 3-stage cp.async.
// MODE 0: QKV epilogue — RoPE via table; q -> hi/lo, k,v -> hi only.
// MODE 1: plain fp32 epilogue to C.
// ---------------------------------------------------------------------------
#define ROWB 80
#define A_BYTES (128 * ROWB)            // 10240
#define STG_BYTES (3 * A_BYTES)         // Ah, Al, Bh = 30720
#define NSTAGE 3
#define GSMEM (NSTAGE * STG_BYTES)      // 92160

__device__ __forceinline__ void fill_stage(uint32_t stg,
        const __half* ah, const __half* al, const __half* bh,
        int k0, int t) {
    int row = t >> 2, cc = t & 3;
    uint32_t so = (uint32_t)(row * ROWB + cc * 16);
    size_t g = (size_t)row * DIMN + k0 + cc * 8;
    cp_async16_s(stg + so,               ah + g);
    cp_async16_s(stg + A_BYTES + so,     al + g);
    cp_async16_s(stg + 2 * A_BYTES + so, bh + g);
}

template <int MODE>
__global__ __launch_bounds__(512)
void hgemm2(const __half* __restrict__ Ah, const __half* __restrict__ Al,
            const __half* __restrict__ Bh,
            float* __restrict__ C,
            __half* __restrict__ qh, __half* __restrict__ ql,
            __half* __restrict__ kh, __half* __restrict__ vh) {
    extern __shared__ char dsm[];
    const uint32_t base = smem_u32(dsm);

    const int t    = threadIdx.x;
    const int lane = t & 31;
    const int warp = t >> 5;              // 0..15
    const int wm   = warp & 3;            // m offset 32*wm
    const int wn   = warp >> 2;           // n offset 32*wn
    const int bm   = blockIdx.y << 7;
    const int bn   = blockIdx.x << 7;     // 128-wide tiles

    const __half* ah0 = Ah + (size_t)bm * DIMN;
    const __half* al0 = Al + (size_t)bm * DIMN;
    const __half* bh0 = Bh + (size_t)bn * DIMN;

    const int nloc = bn & 2047;

    float    acc [2][4][4];
    uint32_t accl[2][4][2];
    #pragma unroll
    for (int mi = 0; mi < 2; mi++)
        #pragma unroll
        for (int ni = 0; ni < 4; ni++) {
            #pragma unroll
            for (int e = 0; e < 4; e++) acc[mi][ni][e] = 0.f;
            accl[mi][ni][0] = 0u; accl[mi][ni][1] = 0u;
        }

    const uint32_t a_lrow  = (uint32_t)(lane & 15);
    const uint32_t a_khalf = (uint32_t)(lane >> 4) * 16;

    fill_stage(base, ah0, al0, bh0, 0, t);
    CP_COMMIT();
    fill_stage(base + STG_BYTES, ah0, al0, bh0, 32, t);
    CP_COMMIT();

    const int NT = DIMN / 32;   // 64
    uint32_t sidx = 0, fidx = 2;
    for (int kt = 0; kt < NT; kt++) {
        if (kt + 2 < NT) {
            fill_stage(base + fidx * STG_BYTES, ah0, al0, bh0,
                       (kt + 2) * 32, t);
            CP_COMMIT();
            asm volatile("cp.async.wait_group 2;\n");
        } else {
            asm volatile("cp.async.wait_group 0;\n");
        }
        __syncthreads();

        const uint32_t stg  = base + sidx * STG_BYTES;
        const uint32_t As_h = stg;
        const uint32_t As_l = stg + A_BYTES;
        const uint32_t Bs_h = stg + 2 * A_BYTES;

        #pragma unroll
        for (int ks = 0; ks < 2; ks++) {
            const uint32_t kb = (uint32_t)ks * 32;
            uint32_t Afh[2][4], Afl[2][4];
            #pragma unroll
            for (int mi = 0; mi < 2; mi++) {
                uint32_t ro = (uint32_t)(wm * 32 + mi * 16) + a_lrow;
                uint32_t off = ro * ROWB + kb + a_khalf;
                ldsm_x4(As_h + off, Afh[mi]);
                ldsm_x4(As_l + off, Afl[mi]);
            }
            #pragma unroll
            for (int nj = 0; nj < 2; nj++) {
                uint32_t ro = (uint32_t)(wn * 32 + nj * 16) + a_lrow;
                uint32_t off = ro * ROWB + kb + a_khalf;
                uint32_t rh[4];
                ldsm_x4(Bs_h + off, rh);
                // hi terms (f32 accum): 4 independent mmas
                mma_f16(acc[0][2*nj],   Afh[0], rh[0], rh[2]);
                mma_f16(acc[1][2*nj],   Afh[1], rh[0], rh[2]);
                mma_f16(acc[0][2*nj+1], Afh[0], rh[1], rh[3]);
                mma_f16(acc[1][2*nj+1], Afh[1], rh[1], rh[3]);
                // lo terms (f16 accum, scaled)
                mma_f16h(accl[0][2*nj],   Afl[0], rh[0], rh[2]);
                mma_f16h(accl[1][2*nj],   Afl[1], rh[0], rh[2]);
                mma_f16h(accl[0][2*nj+1], Afl[0], rh[1], rh[3]);
                mma_f16h(accl[1][2*nj+1], Afl[1], rh[1], rh[3]);
            }
        }
        __syncthreads();

        sidx = (sidx + 1 == NSTAGE) ? 0 : sidx + 1;
        fidx = (fidx + 1 == NSTAGE) ? 0 : fidx + 1;
    }

    // fold lo into fp32 acc
    #pragma unroll
    for (int mi = 0; mi < 2; mi++)
        #pragma unroll
        for (int ni = 0; ni < 4; ni++)
            flush_lo(acc[mi][ni], accl[mi][ni]);

    const int gr = lane >> 2, tg = lane & 3;
    if (MODE == 1) {
        #pragma unroll
        for (int mi = 0; mi < 2; mi++) {
            #pragma unroll
            for (int ni = 0; ni < 4; ni++) {
                const int m = bm + wm * 32 + mi * 16 + gr;
                const int n = nloc + wn * 32 + ni * 8 + tg * 2;
                *(float2*)(C + (size_t)m * DIMN + n) =
                    make_float2(acc[mi][ni][0], acc[mi][ni][1]);
                *(float2*)(C + (size_t)(m + 8) * DIMN + n) =
                    make_float2(acc[mi][ni][2], acc[mi][ni][3]);
            }
        }
    } else {
        const int gm = bn >> 11;                 // 0=q, 1=k, 2=v
        const bool dorope = (gm < 2);
        #pragma unroll
        for (int mi = 0; mi < 2; mi++) {
            #pragma unroll
            for (int ni = 0; ni < 4; ni++) {
                const int n  = nloc + wn * 32 + ni * 8 + tg * 2;
                const int r0 = bm + wm * 32 + mi * 16 + gr;
                float v0 = acc[mi][ni][0], v1 = acc[mi][ni][1];
                float v2 = acc[mi][ni][2], v3 = acc[mi][ni][3];
                if (dorope) {
                    int dp = (n >> 1) & 63;
                    float2 c0 = g_rope[(size_t)(r0 & (SS - 1)) * 64 + dp];
                    float2 c1 = g_rope[(size_t)((r0 + 8) & (SS - 1)) * 64 + dp];
                    float t0 = v0 * c0.x - v1 * c0.y, t1 = v0 * c0.y + v1 * c0.x;
                    v0 = t0; v1 = t1;
                    float t2 = v2 * c1.x - v3 * c1.y, t3 = v2 * c1.y + v3 * c1.x;
                    v2 = t2; v3 = t3;
                }
                size_t o0 = (size_t)r0 * DIMN + n;
                size_t o1 = (size_t)(r0 + 8) * DIMN + n;
                if (gm == 0) {
                    split_store(qh, ql, o0, v0, v1);
                    split_store(qh, ql, o1, v2, v3);
                } else {
                    __half* dst = (gm == 1) ? kh : vh;
                    *(__half2*)(dst + o0) = __floats2half2_rn(v0, v1);
                    *(__half2*)(dst + o1) = __floats2half2_rn(v2, v3);
                }
            }
        }
    }
}

// ---------------------------------------------------------------------------
// flash2: fp16 2-term tensor-core causal flash attention, BM=BN=64, 256 thr.
// Hi terms f32-accum; lo terms f16-accum (scaled), flushed per tile.
// ---------------------------------------------------------------------------
#define FRB 272                 // Q/K/V smem row bytes (128 fp16 + 16 pad)
#define PRB 144                 // P smem row bytes (64 fp16 + 16 pad)
#define SST 66                  // Ss fp32 stride
#define OFF_QH 0
#define OFF_QL 17408
#define OFF_KH 34816
#define OFF_VH 52224
#define OFF_SSX 69632
#define OFF_PH 86528
#define OFF_PL 95744
#define OFF_CORR 104960
#define OFF_LINV 105216
#define FLASH2_SMEM 105472

__global__ __launch_bounds__(256, 1)
void flash2(const __half* __restrict__ Qh, const __half* __restrict__ Ql,
            const __half* __restrict__ Kh, const __half* __restrict__ Vh,
            __half* __restrict__ Ath, __half* __restrict__ Atl) {
    extern __shared__ char fsm[];
    const uint32_t base = smem_u32(fsm);
    float* Ssf    = (float*)(fsm + OFF_SSX);
    float* scorrf = (float*)(fsm + OFF_CORR);
    float* linvf  = (float*)(fsm + OFF_LINV);
    __half* Psh = (__half*)(fsm + OFF_PH);
    __half* Psl = (__half*)(fsm + OFF_PL);

    const int t = threadIdx.x, lane = t & 31, warp = t >> 5;
    const int qt = blockIdx.x, h = blockIdx.y, b = blockIdx.z;
    const int q0 = qt * 64;
    const float scale = 0.08838834764831845f;   // 1/sqrt(128)

    const size_t hoff = ((size_t)b * SS) * DIMN + (size_t)h * HDD;
    const __half* qhp = Qh + hoff;
    const __half* qlp = Ql + hoff;
    const __half* khp = Kh + hoff;
    const __half* vhp = Vh + hoff;

    #pragma unroll
    for (int i = 0; i < 4; i++) {
        int c = t + (i << 8);
        int row = c >> 4, cc = c & 15;
        uint32_t so = (uint32_t)(row * FRB + cc * 16);
        size_t g = (size_t)(q0 + row) * DIMN + cc * 8;
        cp_async16_s(base + OFF_QH + so, qhp + g);
        cp_async16_s(base + OFF_QL + so, qlp + g);
    }
    CP_COMMIT();

    const int m0  = (warp >> 1) * 16;
    const int n0q = (warp & 1) * 32;
    const int n0p = (warp & 1) * 64;
    const int gr = lane >> 2, tg = lane & 3;
    const int sr = t >> 2, q4 = t & 3;

    const uint32_t a_lrow = (uint32_t)(lane & 15);
    const uint32_t a_kh   = (uint32_t)(lane >> 4) * 16;

    float oacc[8][4];
    #pragma unroll
    for (int ni = 0; ni < 8; ni++)
        #pragma unroll
        for (int e = 0; e < 4; e++) oacc[ni][e] = 0.f;
    float mval = -CUDART_INF_F, lval = 0.f;

    for (int kt = 0; kt <= qt; kt++) {
        const int k0 = kt * 64;
        __syncthreads();
        #pragma unroll
        for (int i = 0; i < 4; i++) {
            int c = t + (i << 8);
            int row = c >> 4, cc = c & 15;
            uint32_t so = (uint32_t)(row * FRB + cc * 16);
            size_t g = (size_t)(k0 + row) * DIMN + cc * 8;
            cp_async16_s(base + OFF_KH + so, khp + g);
            cp_async16_s(base + OFF_VH + so, vhp + g);
        }
        CP_COMMIT();
        asm volatile("cp.async.wait_group 0;\n");
        __syncthreads();

        // ---- QK^T: hi f32-accum, lo f16-accum ----
        float    sacc [4][4];
        uint32_t saccl[4][2];
        #pragma unroll
        for (int ni = 0; ni < 4; ni++) {
            #pragma unroll
            for (int e = 0; e < 4; e++) sacc[ni][e] = 0.f;
            saccl[ni][0] = 0u; saccl[ni][1] = 0u;
        }
        #pragma unroll
        for (int ks = 0; ks < 8; ks++) {
            const uint32_t kb = (uint32_t)ks * 32;
            uint32_t Bfh[4][2];
            #pragma unroll
            for (int nj = 0; nj < 2; nj++) {
                uint32_t ro = (uint32_t)(n0q + nj * 16) + a_lrow;
                uint32_t off = ro * FRB + kb + a_kh;
                uint32_t rh[4];
                ldsm_x4(base + OFF_KH + off, rh);
                Bfh[2*nj][0] = rh[0]; Bfh[2*nj][1] = rh[2];
                Bfh[2*nj+1][0] = rh[1]; Bfh[2*nj+1][1] = rh[3];
            }
            uint32_t aoff = (uint32_t)(m0 + a_lrow) * FRB + kb + a_kh;
            uint32_t Afh[4], Afl[4];
            ldsm_x4(base + OFF_QH + aoff, Afh);
            ldsm_x4(base + OFF_QL + aoff, Afl);
            #pragma unroll
            for (int ni = 0; ni < 4; ni++)
                mma_f16(sacc[ni], Afh, Bfh[ni][0], Bfh[ni][1]);
            #pragma unroll
            for (int ni = 0; ni < 4; ni++)
                mma_f16h(saccl[ni], Afl, Bfh[ni][0], Bfh[ni][1]);
        }
        #pragma unroll
        for (int ni = 0; ni < 4; ni++) {
            flush_lo(sacc[ni], saccl[ni]);
            int cn = n0q + ni * 8 + tg * 2;
            int r0 = m0 + gr, r1 = r0 + 8;
            float s0 = sacc[ni][0] * scale, s1 = sacc[ni][1] * scale;
            float s2 = sacc[ni][2] * scale, s3 = sacc[ni][3] * scale;
            if (k0 + cn     > q0 + r0) s0 = -CUDART_INF_F;
            if (k0 + cn + 1 > q0 + r0) s1 = -CUDART_INF_F;
            if (k0 + cn     > q0 + r1) s2 = -CUDART_INF_F;
            if (k0 + cn + 1 > q0 + r1) s3 = -CUDART_INF_F;
            Ssf[r0 * SST + cn]     = s0;
            Ssf[r0 * SST + cn + 1] = s1;
            Ssf[r1 * SST + cn]     = s2;
            Ssf[r1 * SST + cn + 1] = s3;
        }
        __syncthreads();

        // ---- online softmax (quad per row), emit P fp16 hi + scaled lo ----
        {
            float* srow = Ssf + sr * SST + q4 * 16;
            float mloc = -CUDART_INF_F;
            #pragma unroll
            for (int j = 0; j < 16; j++) mloc = fmaxf(mloc, srow[j]);
            mloc = fmaxf(mloc, __shfl_xor_sync(0xFFFFFFFFu, mloc, 1));
            mloc = fmaxf(mloc, __shfl_xor_sync(0xFFFFFFFFu, mloc, 2));
            float mnew = fmaxf(mval, mloc);
            float corr = __expf(mval - mnew);
            if (q4 == 0) scorrf[sr] = corr;
            __half* php = Psh + sr * (PRB / 2) + q4 * 16;
            __half* plp = Psl + sr * (PRB / 2) + q4 * 16;
            float lloc = 0.f;
            #pragma unroll
            for (int j = 0; j < 16; j++) {
                float p = __expf(srow[j] - mnew);
                __half ph = __float2half(p);
                php[j] = ph;
                plp[j] = __float2half((p - __half2float(ph)) * LO_SCALE);
                lloc += p;
            }
            lloc += __shfl_xor_sync(0xFFFFFFFFu, lloc, 1);
            lloc += __shfl_xor_sync(0xFFFFFFFFu, lloc, 2);
            lval = lval * corr + lloc;
            mval = mnew;
        }
        __syncthreads();

        // ---- rescale, then P@V: hi f32-accum, lo f16-accum (per-tile) ----
        {
            float c0 = scorrf[m0 + gr], c1 = scorrf[m0 + gr + 8];
            #pragma unroll
            for (int ni = 0; ni < 8; ni++) {
                oacc[ni][0] *= c0; oacc[ni][1] *= c0;
                oacc[ni][2] *= c1; oacc[ni][3] *= c1;
            }
        }
        uint32_t oaccl[8][2];
        #pragma unroll
        for (int ni = 0; ni < 8; ni++) { oaccl[ni][0] = 0u; oaccl[ni][1] = 0u; }
        #pragma unroll
        for (int ks = 0; ks < 4; ks++) {
            uint32_t aoff = (uint32_t)(m0 + a_lrow) * PRB + (uint32_t)ks * 32 + a_kh;
            uint32_t Afh[4], Afl[4];
            ldsm_x4(base + OFF_PH + aoff, Afh);
            ldsm_x4(base + OFF_PL + aoff, Afl);
            uint32_t vrow = (uint32_t)(ks * 16) + a_lrow;
            uint32_t vhr[4][4];
            #pragma unroll
            for (int nj = 0; nj < 4; nj++) {
                uint32_t boff = vrow * FRB +
                    (uint32_t)(n0p + nj * 16 + ((lane >> 4) << 3)) * 2;
                ldsm_x4_t(base + OFF_VH + boff, vhr[nj]);
            }
            #pragma unroll
            for (int nj = 0; nj < 4; nj++) {
                mma_f16(oacc[2*nj],   Afh, vhr[nj][0], vhr[nj][1]);
                mma_f16(oacc[2*nj+1], Afh, vhr[nj][2], vhr[nj][3]);
            }
            #pragma unroll
            for (int nj = 0; nj < 4; nj++) {
                mma_f16h(oaccl[2*nj],   Afl, vhr[nj][0], vhr[nj][1]);
                mma_f16h(oaccl[2*nj+1], Afl, vhr[nj][2], vhr[nj][3]);
            }
        }
        #pragma unroll
        for (int ni = 0; ni < 8; ni++) flush_lo(oacc[ni], oaccl[ni]);
    }

    __syncthreads();
    if (q4 == 0) linvf[sr] = 1.f / lval;
    __syncthreads();

    const float i0v = linvf[m0 + gr], i1v = linvf[m0 + gr + 8];
    __half* ath = Ath + hoff;
    __half* atl = Atl + hoff;
    #pragma unroll
    for (int ni = 0; ni < 8; ni++) {
        int col = n0p + ni * 8 + tg * 2;
        split_store(ath, atl, (size_t)(q0 + m0 + gr) * DIMN + col,
                    oacc[ni][0] * i0v, oacc[ni][1] * i0v);
        split_store(ath, atl, (size_t)(q0 + m0 + gr + 8) * DIMN + col,
                    oacc[ni][2] * i1v, oacc[ni][3] * i1v);
    }
}

// ---------------------------------------------------------------------------
extern "C" void kernel_launch(void* const* d_in, const int* in_sizes, int n_in,
                              void* d_out, int out_size) {
    const float* x  = (const float*)d_in[0];
    const float* Wq = (const float*)d_in[1];
    const float* Wk = (const float*)d_in[2];
    const float* Wv = (const float*)d_in[3];
    const float* Wo = (const float*)d_in[4];
    float* out = (float*)d_out;

    __half *xh, *xl, *ath, *atl, *wth, *qh, *ql, *kh, *vh;
    cudaGetSymbolAddress((void**)&xh,  g_xh);
    cudaGetSymbolAddress((void**)&xl,  g_xl);
    cudaGetSymbolAddress((void**)&ath, g_ath);
    cudaGetSymbolAddress((void**)&atl, g_atl);
    cudaGetSymbolAddress((void**)&wth, g_wth);
    cudaGetSymbolAddress((void**)&qh,  g_qh);
    cudaGetSymbolAddress((void**)&ql,  g_ql);
    cudaGetSymbolAddress((void**)&kh,  g_kh);
    cudaGetSymbolAddress((void**)&vh,  g_vh);
    const size_t WSZ = (size_t)DIMN * DIMN;

    cudaFuncSetAttribute(hgemm2<0>,
                         cudaFuncAttributeMaxDynamicSharedMemorySize, GSMEM);
    cudaFuncSetAttribute(hgemm2<1>,
                         cudaFuncAttributeMaxDynamicSharedMemorySize, GSMEM);
    cudaFuncSetAttribute(flash2,
                         cudaFuncAttributeMaxDynamicSharedMemorySize, FLASH2_SMEM);

    // idx 0-2: prep; idx 3 = fused QKV GEMM (ncu capture slot)
    split_rows<<<(MTOT * DIMN) / 1024, 256>>>(x, xh, xl);
    dim3 tga(DIMN / 32, DIMN / 32, 4), tb(32, 8);
    split_transpose_all<<<tga, tb>>>(Wq, Wk, Wv, Wo, wth);
    rope_table<<<(SS * 64) / 256, 256>>>();

    dim3 gqkv(3 * DIMN / 128, MTOT / 128);   // (48, 32)
    hgemm2<0><<<gqkv, 512, GSMEM>>>(xh, xl, wth, nullptr, qh, ql, kh, vh);

    flash2<<<dim3(SS / 64, HH, BB), 256, FLASH2_SMEM>>>(qh, ql, kh, vh,
                                                        ath, atl);

    dim3 go(DIMN / 128, MTOT / 128);         // (16, 32)
    hgemm2<1><<<go, 512, GSMEM>>>(ath, atl, wth + 3 * WSZ, out,
                                  nullptr, nullptr, nullptr, nullptr);
}

// round 15
// speedup vs baseline: 1.5057x; 1.5057x over previous
#include <cuda_runtime.h>
#include <cuda_fp16.h>
#include <math_constants.h>
#include <math.h>
#include <cstdint>

#define DIMN 2048
#define BB 2
#define SS 2048
#define HH 16
#define HDD 128
#define MTOT (BB*SS)   // 4096

// ---------------------------------------------------------------------------
// Scratch (alloc-free rule: __device__ globals)
// ---------------------------------------------------------------------------
__device__ __half g_xh[(size_t)MTOT * DIMN];
__device__ __half g_ath[(size_t)MTOT * DIMN];
__device__ __half g_atl[(size_t)MTOT * DIMN];
__device__ __half g_wth[4][(size_t)DIMN * DIMN];   // W^T hi, [N][K]
__device__ __half g_qh[(size_t)MTOT * DIMN];
__device__ __half g_ql[(size_t)MTOT * DIMN];
__device__ __half g_kh[(size_t)MTOT * DIMN];
__device__ __half g_vh[(size_t)MTOT * DIMN];
__device__ float2 g_rope[(size_t)SS * 64];         // (cos, sin) per (s, dp)

// ---------------------------------------------------------------------------
// PTX helpers (generic sm_80+ features only)
// ---------------------------------------------------------------------------
__device__ __forceinline__ void cp_async16_s(uint32_t s, const void* g) {
    asm volatile("cp.async.cg.shared.global [%0], [%1], 16;\n" :: "r"(s), "l"(g));
}
#define CP_COMMIT() asm volatile("cp.async.commit_group;\n")

__device__ __forceinline__ uint32_t smem_u32(const void* p) {
    uint32_t a;
    asm("{ .reg .u64 t; cvta.to.shared.u64 t, %1; cvt.u32.u64 %0, t; }"
        : "=r"(a) : "l"(p));
    return a;
}

__device__ __forceinline__ void ldsm_x4(uint32_t addr, uint32_t* r) {
    asm volatile("ldmatrix.sync.aligned.m8n8.x4.shared.b16 {%0,%1,%2,%3}, [%4];"
                 : "=r"(r[0]), "=r"(r[1]), "=r"(r[2]), "=r"(r[3]) : "r"(addr));
}
__device__ __forceinline__ void ldsm_x4_t(uint32_t addr, uint32_t* r) {
    asm volatile("ldmatrix.sync.aligned.m8n8.x4.trans.shared.b16 {%0,%1,%2,%3}, [%4];"
                 : "=r"(r[0]), "=r"(r[1]), "=r"(r[2]), "=r"(r[3]) : "r"(addr));
}

__device__ __forceinline__ void mma_f16(float* d, const uint32_t* a,
                                        uint32_t b0, uint32_t b1) {
    asm volatile(
        "mma.sync.aligned.m16n8k16.row.col.f32.f16.f16.f32 "
        "{%0,%1,%2,%3}, {%4,%5,%6,%7}, {%8,%9}, {%0,%1,%2,%3};"
        : "+f"(d[0]), "+f"(d[1]), "+f"(d[2]), "+f"(d[3])
        : "r"(a[0]), "r"(a[1]), "r"(a[2]), "r"(a[3]), "r"(b0), "r"(b1));
}

__device__ __forceinline__ void split_store(__half* h, __half* l,
                                            size_t off, float v0, float v1) {
    __half h0 = __float2half(v0), h1 = __float2half(v1);
    *(__half2*)(h + off) = __half2(h0, h1);
    *(__half2*)(l + off) = __half2(
        __float2half(v0 - __half2float(h0)),
        __float2half(v1 - __half2float(h1)));
}

// ---------------------------------------------------------------------------
// Prep: convert fp32 rows to fp16 (hi only)
// ---------------------------------------------------------------------------
__global__ void cvt_rows(const float* __restrict__ in,
                         __half* __restrict__ h) {
    size_t i = ((size_t)blockIdx.x * 256 + threadIdx.x) * 4;
    float4 v = *(const float4*)(in + i);
    *(__half2*)(h + i)     = __floats2half2_rn(v.x, v.y);
    *(__half2*)(h + i + 2) = __floats2half2_rn(v.z, v.w);
}

// ---------------------------------------------------------------------------
// Prep: transpose all 4 weights (blockIdx.z selects) -> W^T fp16 hi
// ---------------------------------------------------------------------------
__global__ void split_transpose_all(const float* __restrict__ W0,
                                    const float* __restrict__ W1,
                                    const float* __restrict__ W2,
                                    const float* __restrict__ W3,
                                    __half* __restrict__ th) {
    __shared__ float ts[32][33];
    const float* W = (blockIdx.z == 0) ? W0 : (blockIdx.z == 1) ? W1
                   : (blockIdx.z == 2) ? W2 : W3;
    const size_t mo = (size_t)blockIdx.z * DIMN * DIMN;
    const int bx = blockIdx.x * 32, by = blockIdx.y * 32;
    const int tx = threadIdx.x, ty = threadIdx.y;   // 32 x 8
    #pragma unroll
    for (int j = 0; j < 4; j++)
        ts[ty + 8 * j][tx] = W[(size_t)(by + ty + 8 * j) * DIMN + bx + tx];
    __syncthreads();
    #pragma unroll
    for (int j = 0; j < 4; j++) {
        float v = ts[tx][ty + 8 * j];
        th[mo + (size_t)(bx + ty + 8 * j) * DIMN + by + tx] = __float2half(v);
    }
}

// ---------------------------------------------------------------------------
// Prep: RoPE cos/sin table  g_rope[s][dp]
// ---------------------------------------------------------------------------
__global__ void rope_table() {
    int idx = blockIdx.x * 256 + threadIdx.x;    // 0 .. SS*64-1
    int s = idx >> 6, dp = idx & 63;
    float inv = powf(10000.0f, -(float)dp * (1.0f / 64.0f));
    float sn, cs;
    sincosf((float)s * inv, &sn, &cs);
    g_rope[idx] = make_float2(cs, sn);
}

// ---------------------------------------------------------------------------
// fp16 split GEMM: C = Ah@Bh^T [+ Al@Bh^T if TERMS==2]. B hi only.
// Block tile 128x256, BK=32, 512 threads (16 warps, warp tile 32x64),
// 3-stage cp.async, term-grouped mma.
// MODE 0: QKV epilogue — RoPE via table; q -> hi/lo, k,v -> hi only.
// MODE 1: plain fp32 epilogue to C.
// ---------------------------------------------------------------------------
#define ROWB 80
#define A_BYTES (128 * ROWB)            // 10240
#define B_BYTES (256 * ROWB)            // 20480
#define STG_BYTES (2 * A_BYTES + B_BYTES)   // 40960
#define NSTAGE 3
#define GSMEM (NSTAGE * STG_BYTES)      // 122880

template <int TERMS>
__device__ __forceinline__ void fill_stage(uint32_t stg,
        const __half* ah, const __half* al, const __half* bh,
        int k0, int t) {
    {
        int row = t >> 2, cc = t & 3;
        uint32_t so = (uint32_t)(row * ROWB + cc * 16);
        size_t g = (size_t)row * DIMN + k0 + cc * 8;
        cp_async16_s(stg + so, ah + g);
        if (TERMS == 2) cp_async16_s(stg + A_BYTES + so, al + g);
    }
    #pragma unroll
    for (int i = 0; i < 2; i++) {
        int c = t + (i << 9);
        int row = c >> 2, cc = c & 3;
        uint32_t so = (uint32_t)(row * ROWB + cc * 16);
        size_t g = (size_t)row * DIMN + k0 + cc * 8;
        cp_async16_s(stg + 2 * A_BYTES + so, bh + g);
    }
}

template <int MODE, int TERMS>
__global__ __launch_bounds__(512)
void hgemm(const __half* __restrict__ Ah, const __half* __restrict__ Al,
           const __half* __restrict__ Bh,
           float* __restrict__ C,
           __half* __restrict__ qh, __half* __restrict__ ql,
           __half* __restrict__ kh, __half* __restrict__ vh) {
    extern __shared__ char dsm[];
    const uint32_t base = smem_u32(dsm);

    const int t    = threadIdx.x;
    const int lane = t & 31;
    const int warp = t >> 5;              // 0..15
    const int wm   = warp & 3;            // m offset 32*wm
    const int wn   = warp >> 2;           // n offset 64*wn
    const int bm   = blockIdx.y << 7;
    const int bn   = blockIdx.x << 8;     // 256-wide tiles

    const __half* ah0 = Ah + (size_t)bm * DIMN;
    const __half* al0 = (TERMS == 2) ? Al + (size_t)bm * DIMN : nullptr;
    const __half* bh0 = Bh + (size_t)bn * DIMN;

    const int nloc = bn & 2047;

    float acc[2][8][4];
    #pragma unroll
    for (int mi = 0; mi < 2; mi++)
        #pragma unroll
        for (int ni = 0; ni < 8; ni++)
            #pragma unroll
            for (int e = 0; e < 4; e++) acc[mi][ni][e] = 0.f;

    const uint32_t a_lrow  = (uint32_t)(lane & 15);
    const uint32_t a_khalf = (uint32_t)(lane >> 4) * 16;

    fill_stage<TERMS>(base, ah0, al0, bh0, 0, t);
    CP_COMMIT();
    fill_stage<TERMS>(base + STG_BYTES, ah0, al0, bh0, 32, t);
    CP_COMMIT();

    const int NT = DIMN / 32;   // 64
    uint32_t sidx = 0, fidx = 2;
    for (int kt = 0; kt < NT; kt++) {
        if (kt + 2 < NT) {
            fill_stage<TERMS>(base + fidx * STG_BYTES, ah0, al0, bh0,
                              (kt + 2) * 32, t);
            CP_COMMIT();
            asm volatile("cp.async.wait_group 2;\n");
        } else {
            asm volatile("cp.async.wait_group 0;\n");
        }
        __syncthreads();

        const uint32_t stg  = base + sidx * STG_BYTES;
        const uint32_t As_h = stg;
        const uint32_t As_l = stg + A_BYTES;
        const uint32_t Bs_h = stg + 2 * A_BYTES;

        #pragma unroll
        for (int ks = 0; ks < 2; ks++) {
            const uint32_t kb = (uint32_t)ks * 32;
            uint32_t Afh[2][4], Afl[2][4];
            #pragma unroll
            for (int mi = 0; mi < 2; mi++) {
                uint32_t ro = (uint32_t)(wm * 32 + mi * 16) + a_lrow;
                uint32_t off = ro * ROWB + kb + a_khalf;
                ldsm_x4(As_h + off, Afh[mi]);
                if (TERMS == 2) ldsm_x4(As_l + off, Afl[mi]);
            }
            #pragma unroll
            for (int nj = 0; nj < 4; nj++) {
                uint32_t ro = (uint32_t)(wn * 64 + nj * 16) + a_lrow;
                uint32_t off = ro * ROWB + kb + a_khalf;
                uint32_t rh[4];
                ldsm_x4(Bs_h + off, rh);
                // term Ah*Bh: 4 independent mmas
                mma_f16(acc[0][2*nj],   Afh[0], rh[0], rh[2]);
                mma_f16(acc[1][2*nj],   Afh[1], rh[0], rh[2]);
                mma_f16(acc[0][2*nj+1], Afh[0], rh[1], rh[3]);
                mma_f16(acc[1][2*nj+1], Afh[1], rh[1], rh[3]);
                if (TERMS == 2) {
                    // term Al*Bh
                    mma_f16(acc[0][2*nj],   Afl[0], rh[0], rh[2]);
                    mma_f16(acc[1][2*nj],   Afl[1], rh[0], rh[2]);
                    mma_f16(acc[0][2*nj+1], Afl[0], rh[1], rh[3]);
                    mma_f16(acc[1][2*nj+1], Afl[1], rh[1], rh[3]);
                }
            }
        }
        __syncthreads();

        sidx = (sidx + 1 == NSTAGE) ? 0 : sidx + 1;
        fidx = (fidx + 1 == NSTAGE) ? 0 : fidx + 1;
    }

    const int gr = lane >> 2, tg = lane & 3;
    if (MODE == 1) {
        #pragma unroll
        for (int mi = 0; mi < 2; mi++) {
            #pragma unroll
            for (int ni = 0; ni < 8; ni++) {
                const int m = bm + wm * 32 + mi * 16 + gr;
                const int n = nloc + wn * 64 + ni * 8 + tg * 2;
                *(float2*)(C + (size_t)m * DIMN + n) =
                    make_float2(acc[mi][ni][0], acc[mi][ni][1]);
                *(float2*)(C + (size_t)(m + 8) * DIMN + n) =
                    make_float2(acc[mi][ni][2], acc[mi][ni][3]);
            }
        }
    } else {
        const int gm = bn >> 11;                 // 0=q, 1=k, 2=v
        const bool dorope = (gm < 2);
        #pragma unroll
        for (int mi = 0; mi < 2; mi++) {
            #pragma unroll
            for (int ni = 0; ni < 8; ni++) {
                const int n  = nloc + wn * 64 + ni * 8 + tg * 2;
                const int r0 = bm + wm * 32 + mi * 16 + gr;
                float v0 = acc[mi][ni][0], v1 = acc[mi][ni][1];
                float v2 = acc[mi][ni][2], v3 = acc[mi][ni][3];
                if (dorope) {
                    int dp = (n >> 1) & 63;
                    float2 c0 = g_rope[(size_t)(r0 & (SS - 1)) * 64 + dp];
                    float2 c1 = g_rope[(size_t)((r0 + 8) & (SS - 1)) * 64 + dp];
                    float t0 = v0 * c0.x - v1 * c0.y, t1 = v0 * c0.y + v1 * c0.x;
                    v0 = t0; v1 = t1;
                    float t2 = v2 * c1.x - v3 * c1.y, t3 = v2 * c1.y + v3 * c1.x;
                    v2 = t2; v3 = t3;
                }
                size_t o0 = (size_t)r0 * DIMN + n;
                size_t o1 = (size_t)(r0 + 8) * DIMN + n;
                if (gm == 0) {
                    split_store(qh, ql, o0, v0, v1);
                    split_store(qh, ql, o1, v2, v3);
                } else {
                    __half* dst = (gm == 1) ? kh : vh;
                    *(__half2*)(dst + o0) = __floats2half2_rn(v0, v1);
                    *(__half2*)(dst + o1) = __floats2half2_rn(v2, v3);
                }
            }
        }
    }
}

// ---------------------------------------------------------------------------
// flash2: fp16 2-term tensor-core causal flash attention, BM=BN=64, 256 thr.
// QK: Q hi/lo x K hi. PV: P hi/lo x V hi. Emits att as fp16 hi/lo.
// ---------------------------------------------------------------------------
#define FRB 272                 // Q/K/V smem row bytes (128 fp16 + 16 pad)
#define PRB 144                 // P smem row bytes (64 fp16 + 16 pad)
#define SST 66                  // Ss fp32 stride
#define OFF_QH 0
#define OFF_QL 17408
#define OFF_KH 34816
#define OFF_VH 52224
#define OFF_SSX 69632
#define OFF_PH 86528
#define OFF_PL 95744
#define OFF_CORR 104960
#define OFF_LINV 105216
#define FLASH2_SMEM 105472

__global__ __launch_bounds__(256, 1)
void flash2(const __half* __restrict__ Qh, const __half* __restrict__ Ql,
            const __half* __restrict__ Kh, const __half* __restrict__ Vh,
            __half* __restrict__ Ath, __half* __restrict__ Atl) {
    extern __shared__ char fsm[];
    const uint32_t base = smem_u32(fsm);
    float* Ssf    = (float*)(fsm + OFF_SSX);
    float* scorrf = (float*)(fsm + OFF_CORR);
    float* linvf  = (float*)(fsm + OFF_LINV);
    __half* Psh = (__half*)(fsm + OFF_PH);
    __half* Psl = (__half*)(fsm + OFF_PL);

    const int t = threadIdx.x, lane = t & 31, warp = t >> 5;
    const int qt = blockIdx.x, h = blockIdx.y, b = blockIdx.z;
    const int q0 = qt * 64;
    const float scale = 0.08838834764831845f;   // 1/sqrt(128)

    const size_t hoff = ((size_t)b * SS) * DIMN + (size_t)h * HDD;
    const __half* qhp = Qh + hoff;
    const __half* qlp = Ql + hoff;
    const __half* khp = Kh + hoff;
    const __half* vhp = Vh + hoff;

    #pragma unroll
    for (int i = 0; i < 4; i++) {
        int c = t + (i << 8);
        int row = c >> 4, cc = c & 15;
        uint32_t so = (uint32_t)(row * FRB + cc * 16);
        size_t g = (size_t)(q0 + row) * DIMN + cc * 8;
        cp_async16_s(base + OFF_QH + so, qhp + g);
        cp_async16_s(base + OFF_QL + so, qlp + g);
    }
    CP_COMMIT();

    const int m0  = (warp >> 1) * 16;
    const int n0q = (warp & 1) * 32;
    const int n0p = (warp & 1) * 64;
    const int gr = lane >> 2, tg = lane & 3;
    const int sr = t >> 2, q4 = t & 3;

    const uint32_t a_lrow = (uint32_t)(lane & 15);
    const uint32_t a_kh   = (uint32_t)(lane >> 4) * 16;

    float oacc[8][4];
    #pragma unroll
    for (int ni = 0; ni < 8; ni++)
        #pragma unroll
        for (int e = 0; e < 4; e++) oacc[ni][e] = 0.f;
    float mval = -CUDART_INF_F, lval = 0.f;

    for (int kt = 0; kt <= qt; kt++) {
        const int k0 = kt * 64;
        __syncthreads();
        #pragma unroll
        for (int i = 0; i < 4; i++) {
            int c = t + (i << 8);
            int row = c >> 4, cc = c & 15;
            uint32_t so = (uint32_t)(row * FRB + cc * 16);
            size_t g = (size_t)(k0 + row) * DIMN + cc * 8;
            cp_async16_s(base + OFF_KH + so, khp + g);
            cp_async16_s(base + OFF_VH + so, vhp + g);
        }
        CP_COMMIT();
        asm volatile("cp.async.wait_group 0;\n");
        __syncthreads();

        // ---- QK^T (2-term), term-grouped ----
        float sacc[4][4];
        #pragma unroll
        for (int ni = 0; ni < 4; ni++)
            #pragma unroll
            for (int e = 0; e < 4; e++) sacc[ni][e] = 0.f;
        #pragma unroll
        for (int ks = 0; ks < 8; ks++) {
            const uint32_t kb = (uint32_t)ks * 32;
            uint32_t Bfh[4][2];
            #pragma unroll
            for (int nj = 0; nj < 2; nj++) {
                uint32_t ro = (uint32_t)(n0q + nj * 16) + a_lrow;
                uint32_t off = ro * FRB + kb + a_kh;
                uint32_t rh[4];
                ldsm_x4(base + OFF_KH + off, rh);
                Bfh[2*nj][0] = rh[0]; Bfh[2*nj][1] = rh[2];
                Bfh[2*nj+1][0] = rh[1]; Bfh[2*nj+1][1] = rh[3];
            }
            uint32_t aoff = (uint32_t)(m0 + a_lrow) * FRB + kb + a_kh;
            uint32_t Afh[4], Afl[4];
            ldsm_x4(base + OFF_QH + aoff, Afh);
            ldsm_x4(base + OFF_QL + aoff, Afl);
            #pragma unroll
            for (int ni = 0; ni < 4; ni++)
                mma_f16(sacc[ni], Afh, Bfh[ni][0], Bfh[ni][1]);
            #pragma unroll
            for (int ni = 0; ni < 4; ni++)
                mma_f16(sacc[ni], Afl, Bfh[ni][0], Bfh[ni][1]);
        }
        #pragma unroll
        for (int ni = 0; ni < 4; ni++) {
            int cn = n0q + ni * 8 + tg * 2;
            int r0 = m0 + gr, r1 = r0 + 8;
            float s0 = sacc[ni][0] * scale, s1 = sacc[ni][1] * scale;
            float s2 = sacc[ni][2] * scale, s3 = sacc[ni][3] * scale;
            if (k0 + cn     > q0 + r0) s0 = -CUDART_INF_F;
            if (k0 + cn + 1 > q0 + r0) s1 = -CUDART_INF_F;
            if (k0 + cn     > q0 + r1) s2 = -CUDART_INF_F;
            if (k0 + cn + 1 > q0 + r1) s3 = -CUDART_INF_F;
            Ssf[r0 * SST + cn]     = s0;
            Ssf[r0 * SST + cn + 1] = s1;
            Ssf[r1 * SST + cn]     = s2;
            Ssf[r1 * SST + cn + 1] = s3;
        }
        __syncthreads();

        // ---- online softmax (quad per row), emit P fp16 hi/lo ----
        {
            float* srow = Ssf + sr * SST + q4 * 16;
            float mloc = -CUDART_INF_F;
            #pragma unroll
            for (int j = 0; j < 16; j++) mloc = fmaxf(mloc, srow[j]);
            mloc = fmaxf(mloc, __shfl_xor_sync(0xFFFFFFFFu, mloc, 1));
            mloc = fmaxf(mloc, __shfl_xor_sync(0xFFFFFFFFu, mloc, 2));
            float mnew = fmaxf(mval, mloc);
            float corr = __expf(mval - mnew);
            if (q4 == 0) scorrf[sr] = corr;
            __half* php = Psh + sr * (PRB / 2) + q4 * 16;
            __half* plp = Psl + sr * (PRB / 2) + q4 * 16;
            float lloc = 0.f;
            #pragma unroll
            for (int j = 0; j < 16; j++) {
                float p = __expf(srow[j] - mnew);
                __half ph = __float2half(p);
                php[j] = ph;
                plp[j] = __float2half(p - __half2float(ph));
                lloc += p;
            }
            lloc += __shfl_xor_sync(0xFFFFFFFFu, lloc, 1);
            lloc += __shfl_xor_sync(0xFFFFFFFFu, lloc, 2);
            lval = lval * corr + lloc;
            mval = mnew;
        }
        __syncthreads();

        // ---- rescale, then P@V (2-term), term-grouped ----
        {
            float c0 = scorrf[m0 + gr], c1 = scorrf[m0 + gr + 8];
            #pragma unroll
            for (int ni = 0; ni < 8; ni++) {
                oacc[ni][0] *= c0; oacc[ni][1] *= c0;
                oacc[ni][2] *= c1; oacc[ni][3] *= c1;
            }
        }
        #pragma unroll
        for (int ks = 0; ks < 4; ks++) {
            uint32_t aoff = (uint32_t)(m0 + a_lrow) * PRB + (uint32_t)ks * 32 + a_kh;
            uint32_t Afh[4], Afl[4];
            ldsm_x4(base + OFF_PH + aoff, Afh);
            ldsm_x4(base + OFF_PL + aoff, Afl);
            uint32_t vrow = (uint32_t)(ks * 16) + a_lrow;
            uint32_t vhr[4][4];
            #pragma unroll
            for (int nj = 0; nj < 4; nj++) {
                uint32_t boff = vrow * FRB +
                    (uint32_t)(n0p + nj * 16 + ((lane >> 4) << 3)) * 2;
                ldsm_x4_t(base + OFF_VH + boff, vhr[nj]);
            }
            // term Ph*Vh
            #pragma unroll
            for (int nj = 0; nj < 4; nj++) {
                mma_f16(oacc[2*nj],   Afh, vhr[nj][0], vhr[nj][1]);
                mma_f16(oacc[2*nj+1], Afh, vhr[nj][2], vhr[nj][3]);
            }
            // term Pl*Vh
            #pragma unroll
            for (int nj = 0; nj < 4; nj++) {
                mma_f16(oacc[2*nj],   Afl, vhr[nj][0], vhr[nj][1]);
                mma_f16(oacc[2*nj+1], Afl, vhr[nj][2], vhr[nj][3]);
            }
        }
    }

    __syncthreads();
    if (q4 == 0) linvf[sr] = 1.f / lval;
    __syncthreads();

    const float i0v = linvf[m0 + gr], i1v = linvf[m0 + gr + 8];
    __half* ath = Ath + hoff;
    __half* atl = Atl + hoff;
    #pragma unroll
    for (int ni = 0; ni < 8; ni++) {
        int col = n0p + ni * 8 + tg * 2;
        split_store(ath, atl, (size_t)(q0 + m0 + gr) * DIMN + col,
                    oacc[ni][0] * i0v, oacc[ni][1] * i0v);
        split_store(ath, atl, (size_t)(q0 + m0 + gr + 8) * DIMN + col,
                    oacc[ni][2] * i1v, oacc[ni][3] * i1v);
    }
}

// ---------------------------------------------------------------------------
extern "C" void kernel_launch(void* const* d_in, const int* in_sizes, int n_in,
                              void* d_out, int out_size) {
    const float* x  = (const float*)d_in[0];
    const float* Wq = (const float*)d_in[1];
    const float* Wk = (const float*)d_in[2];
    const float* Wv = (const float*)d_in[3];
    const float* Wo = (const float*)d_in[4];
    float* out = (float*)d_out;

    __half *xh, *ath, *atl, *wth, *qh, *ql, *kh, *vh;
    cudaGetSymbolAddress((void**)&xh,  g_xh);
    cudaGetSymbolAddress((void**)&ath, g_ath);
    cudaGetSymbolAddress((void**)&atl, g_atl);
    cudaGetSymbolAddress((void**)&wth, g_wth);
    cudaGetSymbolAddress((void**)&qh,  g_qh);
    cudaGetSymbolAddress((void**)&ql,  g_ql);
    cudaGetSymbolAddress((void**)&kh,  g_kh);
    cudaGetSymbolAddress((void**)&vh,  g_vh);
    const size_t WSZ = (size_t)DIMN * DIMN;

    cudaFuncSetAttribute(hgemm<0, 1>,
                         cudaFuncAttributeMaxDynamicSharedMemorySize, GSMEM);
    cudaFuncSetAttribute(hgemm<1, 2>,
                         cudaFuncAttributeMaxDynamicSharedMemorySize, GSMEM);
    cudaFuncSetAttribute(flash2,
                         cudaFuncAttributeMaxDynamicSharedMemorySize, FLASH2_SMEM);

    // idx 0-2: prep; idx 3 = fused QKV GEMM (ncu capture slot)
    cvt_rows<<<(MTOT * DIMN) / 1024, 256>>>(x, xh);
    dim3 tga(DIMN / 32, DIMN / 32, 4), tb(32, 8);
    split_transpose_all<<<tga, tb>>>(Wq, Wk, Wv, Wo, wth);
    rope_table<<<(SS * 64) / 256, 256>>>();

    dim3 gqkv(3 * DIMN / 256, MTOT / 128);   // (24, 32)
    hgemm<0, 1><<<gqkv, 512, GSMEM>>>(xh, nullptr, wth, nullptr,
                                      qh, ql, kh, vh);

    flash2<<<dim3(SS / 64, HH, BB), 256, FLASH2_SMEM>>>(qh, ql, kh, vh,
                                                        ath, atl);

    dim3 go(DIMN / 256, MTOT / 128);         // (8, 32)
    hgemm<1, 2><<<go, 512, GSMEM>>>(ath, atl, wth + 3 * WSZ, out,
                                    nullptr, nullptr, nullptr, nullptr);
}

// round 16
// speedup vs baseline: 1.6993x; 1.1286x over previous
#include <cuda_runtime.h>
#include <cuda_fp16.h>
#include <math_constants.h>
#include <math.h>
#include <cstdint>

#define DIMN 2048
#define BB 2
#define SS 2048
#define HH 16
#define HDD 128
#define MTOT (BB*SS)   // 4096

// ---------------------------------------------------------------------------
// Scratch (alloc-free rule: __device__ globals)
// ---------------------------------------------------------------------------
__device__ __half g_xh[(size_t)MTOT * DIMN];
__device__ __half g_ath[(size_t)MTOT * DIMN];
__device__ __half g_wth[4][(size_t)DIMN * DIMN];   // W^T hi, [N][K]
__device__ __half g_qh[(size_t)MTOT * DIMN];
__device__ __half g_ql[(size_t)MTOT * DIMN];
__device__ __half g_kh[(size_t)MTOT * DIMN];
__device__ __half g_vh[(size_t)MTOT * DIMN];
__device__ float2 g_rope[(size_t)SS * 64];         // (cos, sin) per (s, dp)

// ---------------------------------------------------------------------------
// PTX helpers (generic sm_80+ features only)
// ---------------------------------------------------------------------------
__device__ __forceinline__ void cp_async16_s(uint32_t s, const void* g) {
    asm volatile("cp.async.cg.shared.global [%0], [%1], 16;\n" :: "r"(s), "l"(g));
}
#define CP_COMMIT() asm volatile("cp.async.commit_group;\n")

__device__ __forceinline__ uint32_t smem_u32(const void* p) {
    uint32_t a;
    asm("{ .reg .u64 t; cvta.to.shared.u64 t, %1; cvt.u32.u64 %0, t; }"
        : "=r"(a) : "l"(p));
    return a;
}

__device__ __forceinline__ void ldsm_x4(uint32_t addr, uint32_t* r) {
    asm volatile("ldmatrix.sync.aligned.m8n8.x4.shared.b16 {%0,%1,%2,%3}, [%4];"
                 : "=r"(r[0]), "=r"(r[1]), "=r"(r[2]), "=r"(r[3]) : "r"(addr));
}
__device__ __forceinline__ void ldsm_x4_t(uint32_t addr, uint32_t* r) {
    asm volatile("ldmatrix.sync.aligned.m8n8.x4.trans.shared.b16 {%0,%1,%2,%3}, [%4];"
                 : "=r"(r[0]), "=r"(r[1]), "=r"(r[2]), "=r"(r[3]) : "r"(addr));
}

__device__ __forceinline__ void mma_f16(float* d, const uint32_t* a,
                                        uint32_t b0, uint32_t b1) {
    asm volatile(
        "mma.sync.aligned.m16n8k16.row.col.f32.f16.f16.f32 "
        "{%0,%1,%2,%3}, {%4,%5,%6,%7}, {%8,%9}, {%0,%1,%2,%3};"
        : "+f"(d[0]), "+f"(d[1]), "+f"(d[2]), "+f"(d[3])
        : "r"(a[0]), "r"(a[1]), "r"(a[2]), "r"(a[3]), "r"(b0), "r"(b1));
}

__device__ __forceinline__ void split_store(__half* h, __half* l,
                                            size_t off, float v0, float v1) {
    __half h0 = __float2half(v0), h1 = __float2half(v1);
    *(__half2*)(h + off) = __half2(h0, h1);
    *(__half2*)(l + off) = __half2(
        __float2half(v0 - __half2float(h0)),
        __float2half(v1 - __half2float(h1)));
}

// ---------------------------------------------------------------------------
// Prep: convert fp32 rows to fp16 (hi only)
// ---------------------------------------------------------------------------
__global__ void cvt_rows(const float* __restrict__ in,
                         __half* __restrict__ h) {
    size_t i = ((size_t)blockIdx.x * 256 + threadIdx.x) * 4;
    float4 v = *(const float4*)(in + i);
    *(__half2*)(h + i)     = __floats2half2_rn(v.x, v.y);
    *(__half2*)(h + i + 2) = __floats2half2_rn(v.z, v.w);
}

// ---------------------------------------------------------------------------
// Prep: transpose all 4 weights (blockIdx.z selects) -> W^T fp16 hi
// ---------------------------------------------------------------------------
__global__ void split_transpose_all(const float* __restrict__ W0,
                                    const float* __restrict__ W1,
                                    const float* __restrict__ W2,
                                    const float* __restrict__ W3,
                                    __half* __restrict__ th) {
    __shared__ float ts[32][33];
    const float* W = (blockIdx.z == 0) ? W0 : (blockIdx.z == 1) ? W1
                   : (blockIdx.z == 2) ? W2 : W3;
    const size_t mo = (size_t)blockIdx.z * DIMN * DIMN;
    const int bx = blockIdx.x * 32, by = blockIdx.y * 32;
    const int tx = threadIdx.x, ty = threadIdx.y;   // 32 x 8
    #pragma unroll
    for (int j = 0; j < 4; j++)
        ts[ty + 8 * j][tx] = W[(size_t)(by + ty + 8 * j) * DIMN + bx + tx];
    __syncthreads();
    #pragma unroll
    for (int j = 0; j < 4; j++) {
        float v = ts[tx][ty + 8 * j];
        th[mo + (size_t)(bx + ty + 8 * j) * DIMN + by + tx] = __float2half(v);
    }
}

// ---------------------------------------------------------------------------
// Prep: RoPE cos/sin table  g_rope[s][dp]
// ---------------------------------------------------------------------------
__global__ void rope_table() {
    int idx = blockIdx.x * 256 + threadIdx.x;    // 0 .. SS*64-1
    int s = idx >> 6, dp = idx & 63;
    float inv = powf(10000.0f, -(float)dp * (1.0f / 64.0f));
    float sn, cs;
    sincosf((float)s * inv, &sn, &cs);
    g_rope[idx] = make_float2(cs, sn);
}

// ---------------------------------------------------------------------------
// fp16 split GEMM: C = Ah@Bh^T [+ Al@Bh^T if TERMS==2]. B hi only.
// Block tile 128x256, BK=32, 512 threads (16 warps, warp tile 32x64),
// 3-stage cp.async, term-grouped mma.
// MODE 0: QKV epilogue — RoPE via table; q -> hi/lo, k,v -> hi only.
// MODE 1: plain fp32 epilogue to C.
// ---------------------------------------------------------------------------
#define ROWB 80
#define A_BYTES (128 * ROWB)            // 10240
#define B_BYTES (256 * ROWB)            // 20480
#define STG_BYTES (2 * A_BYTES + B_BYTES)   // 40960
#define NSTAGE 3
#define GSMEM (NSTAGE * STG_BYTES)      // 122880

template <int TERMS>
__device__ __forceinline__ void fill_stage(uint32_t stg,
        const __half* ah, const __half* al, const __half* bh,
        int k0, int t) {
    {
        int row = t >> 2, cc = t & 3;
        uint32_t so = (uint32_t)(row * ROWB + cc * 16);
        size_t g = (size_t)row * DIMN + k0 + cc * 8;
        cp_async16_s(stg + so, ah + g);
        if (TERMS == 2) cp_async16_s(stg + A_BYTES + so, al + g);
    }
    #pragma unroll
    for (int i = 0; i < 2; i++) {
        int c = t + (i << 9);
        int row = c >> 2, cc = c & 3;
        uint32_t so = (uint32_t)(row * ROWB + cc * 16);
        size_t g = (size_t)row * DIMN + k0 + cc * 8;
        cp_async16_s(stg + 2 * A_BYTES + so, bh + g);
    }
}

template <int MODE, int TERMS>
__global__ __launch_bounds__(512)
void hgemm(const __half* __restrict__ Ah, const __half* __restrict__ Al,
           const __half* __restrict__ Bh,
           float* __restrict__ C,
           __half* __restrict__ qh, __half* __restrict__ ql,
           __half* __restrict__ kh, __half* __restrict__ vh) {
    extern __shared__ char dsm[];
    const uint32_t base = smem_u32(dsm);

    const int t    = threadIdx.x;
    const int lane = t & 31;
    const int warp = t >> 5;              // 0..15
    const int wm   = warp & 3;            // m offset 32*wm
    const int wn   = warp >> 2;           // n offset 64*wn
    const int bm   = blockIdx.y << 7;
    const int bn   = blockIdx.x << 8;     // 256-wide tiles

    const __half* ah0 = Ah + (size_t)bm * DIMN;
    const __half* al0 = (TERMS == 2) ? Al + (size_t)bm * DIMN : nullptr;
    const __half* bh0 = Bh + (size_t)bn * DIMN;

    const int nloc = bn & 2047;

    float acc[2][8][4];
    #pragma unroll
    for (int mi = 0; mi < 2; mi++)
        #pragma unroll
        for (int ni = 0; ni < 8; ni++)
            #pragma unroll
            for (int e = 0; e < 4; e++) acc[mi][ni][e] = 0.f;

    const uint32_t a_lrow  = (uint32_t)(lane & 15);
    const uint32_t a_khalf = (uint32_t)(lane >> 4) * 16;

    fill_stage<TERMS>(base, ah0, al0, bh0, 0, t);
    CP_COMMIT();
    fill_stage<TERMS>(base + STG_BYTES, ah0, al0, bh0, 32, t);
    CP_COMMIT();

    const int NT = DIMN / 32;   // 64
    uint32_t sidx = 0, fidx = 2;
    for (int kt = 0; kt < NT; kt++) {
        if (kt + 2 < NT) {
            fill_stage<TERMS>(base + fidx * STG_BYTES, ah0, al0, bh0,
                              (kt + 2) * 32, t);
            CP_COMMIT();
            asm volatile("cp.async.wait_group 2;\n");
        } else {
            asm volatile("cp.async.wait_group 0;\n");
        }
        __syncthreads();

        const uint32_t stg  = base + sidx * STG_BYTES;
        const uint32_t As_h = stg;
        const uint32_t As_l = stg + A_BYTES;
        const uint32_t Bs_h = stg + 2 * A_BYTES;

        #pragma unroll
        for (int ks = 0; ks < 2; ks++) {
            const uint32_t kb = (uint32_t)ks * 32;
            uint32_t Afh[2][4], Afl[2][4];
            #pragma unroll
            for (int mi = 0; mi < 2; mi++) {
                uint32_t ro = (uint32_t)(wm * 32 + mi * 16) + a_lrow;
                uint32_t off = ro * ROWB + kb + a_khalf;
                ldsm_x4(As_h + off, Afh[mi]);
                if (TERMS == 2) ldsm_x4(As_l + off, Afl[mi]);
            }
            #pragma unroll
            for (int nj = 0; nj < 4; nj++) {
                uint32_t ro = (uint32_t)(wn * 64 + nj * 16) + a_lrow;
                uint32_t off = ro * ROWB + kb + a_khalf;
                uint32_t rh[4];
                ldsm_x4(Bs_h + off, rh);
                // term Ah*Bh: 4 independent mmas
                mma_f16(acc[0][2*nj],   Afh[0], rh[0], rh[2]);
                mma_f16(acc[1][2*nj],   Afh[1], rh[0], rh[2]);
                mma_f16(acc[0][2*nj+1], Afh[0], rh[1], rh[3]);
                mma_f16(acc[1][2*nj+1], Afh[1], rh[1], rh[3]);
                if (TERMS == 2) {
                    // term Al*Bh
                    mma_f16(acc[0][2*nj],   Afl[0], rh[0], rh[2]);
                    mma_f16(acc[1][2*nj],   Afl[1], rh[0], rh[2]);
                    mma_f16(acc[0][2*nj+1], Afl[0], rh[1], rh[3]);
                    mma_f16(acc[1][2*nj+1], Afl[1], rh[1], rh[3]);
                }
            }
        }
        __syncthreads();

        sidx = (sidx + 1 == NSTAGE) ? 0 : sidx + 1;
        fidx = (fidx + 1 == NSTAGE) ? 0 : fidx + 1;
    }

    const int gr = lane >> 2, tg = lane & 3;
    if (MODE == 1) {
        #pragma unroll
        for (int mi = 0; mi < 2; mi++) {
            #pragma unroll
            for (int ni = 0; ni < 8; ni++) {
                const int m = bm + wm * 32 + mi * 16 + gr;
                const int n = nloc + wn * 64 + ni * 8 + tg * 2;
                *(float2*)(C + (size_t)m * DIMN + n) =
                    make_float2(acc[mi][ni][0], acc[mi][ni][1]);
                *(float2*)(C + (size_t)(m + 8) * DIMN + n) =
                    make_float2(acc[mi][ni][2], acc[mi][ni][3]);
            }
        }
    } else {
        const int gm = bn >> 11;                 // 0=q, 1=k, 2=v
        const bool dorope = (gm < 2);
        #pragma unroll
        for (int mi = 0; mi < 2; mi++) {
            #pragma unroll
            for (int ni = 0; ni < 8; ni++) {
                const int n  = nloc + wn * 64 + ni * 8 + tg * 2;
                const int r0 = bm + wm * 32 + mi * 16 + gr;
                float v0 = acc[mi][ni][0], v1 = acc[mi][ni][1];
                float v2 = acc[mi][ni][2], v3 = acc[mi][ni][3];
                if (dorope) {
                    int dp = (n >> 1) & 63;
                    float2 c0 = g_rope[(size_t)(r0 & (SS - 1)) * 64 + dp];
                    float2 c1 = g_rope[(size_t)((r0 + 8) & (SS - 1)) * 64 + dp];
                    float t0 = v0 * c0.x - v1 * c0.y, t1 = v0 * c0.y + v1 * c0.x;
                    v0 = t0; v1 = t1;
                    float t2 = v2 * c1.x - v3 * c1.y, t3 = v2 * c1.y + v3 * c1.x;
                    v2 = t2; v3 = t3;
                }
                size_t o0 = (size_t)r0 * DIMN + n;
                size_t o1 = (size_t)(r0 + 8) * DIMN + n;
                if (gm == 0) {
                    split_store(qh, ql, o0, v0, v1);
                    split_store(qh, ql, o1, v2, v3);
                } else {
                    __half* dst = (gm == 1) ? kh : vh;
                    *(__half2*)(dst + o0) = __floats2half2_rn(v0, v1);
                    *(__half2*)(dst + o1) = __floats2half2_rn(v2, v3);
                }
            }
        }
    }
}

// ---------------------------------------------------------------------------
// flash2: fp16 2-term tensor-core causal flash attention, BM=BN=64, 256 thr.
// QK: Q hi/lo x K hi. PV: P hi/lo x V hi. Emits att as fp16 hi only.
// ---------------------------------------------------------------------------
#define FRB 272                 // Q/K/V smem row bytes (128 fp16 + 16 pad)
#define PRB 144                 // P smem row bytes (64 fp16 + 16 pad)
#define SST 66                  // Ss fp32 stride
#define OFF_QH 0
#define OFF_QL 17408
#define OFF_KH 34816
#define OFF_VH 52224
#define OFF_SSX 69632
#define OFF_PH 86528
#define OFF_PL 95744
#define OFF_CORR 104960
#define OFF_LINV 105216
#define FLASH2_SMEM 105472

__global__ __launch_bounds__(256, 1)
void flash2(const __half* __restrict__ Qh, const __half* __restrict__ Ql,
            const __half* __restrict__ Kh, const __half* __restrict__ Vh,
            __half* __restrict__ Ath) {
    extern __shared__ char fsm[];
    const uint32_t base = smem_u32(fsm);
    float* Ssf    = (float*)(fsm + OFF_SSX);
    float* scorrf = (float*)(fsm + OFF_CORR);
    float* linvf  = (float*)(fsm + OFF_LINV);
    __half* Psh = (__half*)(fsm + OFF_PH);
    __half* Psl = (__half*)(fsm + OFF_PL);

    const int t = threadIdx.x, lane = t & 31, warp = t >> 5;
    const int qt = blockIdx.x, h = blockIdx.y, b = blockIdx.z;
    const int q0 = qt * 64;
    const float scale = 0.08838834764831845f;   // 1/sqrt(128)

    const size_t hoff = ((size_t)b * SS) * DIMN + (size_t)h * HDD;
    const __half* qhp = Qh + hoff;
    const __half* qlp = Ql + hoff;
    const __half* khp = Kh + hoff;
    const __half* vhp = Vh + hoff;

    #pragma unroll
    for (int i = 0; i < 4; i++) {
        int c = t + (i << 8);
        int row = c >> 4, cc = c & 15;
        uint32_t so = (uint32_t)(row * FRB + cc * 16);
        size_t g = (size_t)(q0 + row) * DIMN + cc * 8;
        cp_async16_s(base + OFF_QH + so, qhp + g);
        cp_async16_s(base + OFF_QL + so, qlp + g);
    }
    CP_COMMIT();

    const int m0  = (warp >> 1) * 16;
    const int n0q = (warp & 1) * 32;
    const int n0p = (warp & 1) * 64;
    const int gr = lane >> 2, tg = lane & 3;
    const int sr = t >> 2, q4 = t & 3;

    const uint32_t a_lrow = (uint32_t)(lane & 15);
    const uint32_t a_kh   = (uint32_t)(lane >> 4) * 16;

    float oacc[8][4];
    #pragma unroll
    for (int ni = 0; ni < 8; ni++)
        #pragma unroll
        for (int e = 0; e < 4; e++) oacc[ni][e] = 0.f;
    float mval = -CUDART_INF_F, lval = 0.f;

    for (int kt = 0; kt <= qt; kt++) {
        const int k0 = kt * 64;
        __syncthreads();
        #pragma unroll
        for (int i = 0; i < 4; i++) {
            int c = t + (i << 8);
            int row = c >> 4, cc = c & 15;
            uint32_t so = (uint32_t)(row * FRB + cc * 16);
            size_t g = (size_t)(k0 + row) * DIMN + cc * 8;
            cp_async16_s(base + OFF_KH + so, khp + g);
            cp_async16_s(base + OFF_VH + so, vhp + g);
        }
        CP_COMMIT();
        asm volatile("cp.async.wait_group 0;\n");
        __syncthreads();

        // ---- QK^T (2-term), term-grouped ----
        float sacc[4][4];
        #pragma unroll
        for (int ni = 0; ni < 4; ni++)
            #pragma unroll
            for (int e = 0; e < 4; e++) sacc[ni][e] = 0.f;
        #pragma unroll
        for (int ks = 0; ks < 8; ks++) {
            const uint32_t kb = (uint32_t)ks * 32;
            uint32_t Bfh[4][2];
            #pragma unroll
            for (int nj = 0; nj < 2; nj++) {
                uint32_t ro = (uint32_t)(n0q + nj * 16) + a_lrow;
                uint32_t off = ro * FRB + kb + a_kh;
                uint32_t rh[4];
                ldsm_x4(base + OFF_KH + off, rh);
                Bfh[2*nj][0] = rh[0]; Bfh[2*nj][1] = rh[2];
                Bfh[2*nj+1][0] = rh[1]; Bfh[2*nj+1][1] = rh[3];
            }
            uint32_t aoff = (uint32_t)(m0 + a_lrow) * FRB + kb + a_kh;
            uint32_t Afh[4], Afl[4];
            ldsm_x4(base + OFF_QH + aoff, Afh);
            ldsm_x4(base + OFF_QL + aoff, Afl);
            #pragma unroll
            for (int ni = 0; ni < 4; ni++)
                mma_f16(sacc[ni], Afh, Bfh[ni][0], Bfh[ni][1]);
            #pragma unroll
            for (int ni = 0; ni < 4; ni++)
                mma_f16(sacc[ni], Afl, Bfh[ni][0], Bfh[ni][1]);
        }
        #pragma unroll
        for (int ni = 0; ni < 4; ni++) {
            int cn = n0q + ni * 8 + tg * 2;
            int r0 = m0 + gr, r1 = r0 + 8;
            float s0 = sacc[ni][0] * scale, s1 = sacc[ni][1] * scale;
            float s2 = sacc[ni][2] * scale, s3 = sacc[ni][3] * scale;
            if (k0 + cn     > q0 + r0) s0 = -CUDART_INF_F;
            if (k0 + cn + 1 > q0 + r0) s1 = -CUDART_INF_F;
            if (k0 + cn     > q0 + r1) s2 = -CUDART_INF_F;
            if (k0 + cn + 1 > q0 + r1) s3 = -CUDART_INF_F;
            Ssf[r0 * SST + cn]     = s0;
            Ssf[r0 * SST + cn + 1] = s1;
            Ssf[r1 * SST + cn]     = s2;
            Ssf[r1 * SST + cn + 1] = s3;
        }
        __syncthreads();

        // ---- online softmax (quad per row), emit P fp16 hi/lo ----
        {
            float* srow = Ssf + sr * SST + q4 * 16;
            float mloc = -CUDART_INF_F;
            #pragma unroll
            for (int j = 0; j < 16; j++) mloc = fmaxf(mloc, srow[j]);
            mloc = fmaxf(mloc, __shfl_xor_sync(0xFFFFFFFFu, mloc, 1));
            mloc = fmaxf(mloc, __shfl_xor_sync(0xFFFFFFFFu, mloc, 2));
            float mnew = fmaxf(mval, mloc);
            float corr = __expf(mval - mnew);
            if (q4 == 0) scorrf[sr] = corr;
            __half* php = Psh + sr * (PRB / 2) + q4 * 16;
            __half* plp = Psl + sr * (PRB / 2) + q4 * 16;
            float lloc = 0.f;
            #pragma unroll
            for (int j = 0; j < 16; j++) {
                float p = __expf(srow[j] - mnew);
                __half ph = __float2half(p);
                php[j] = ph;
                plp[j] = __float2half(p - __half2float(ph));
                lloc += p;
            }
            lloc += __shfl_xor_sync(0xFFFFFFFFu, lloc, 1);
            lloc += __shfl_xor_sync(0xFFFFFFFFu, lloc, 2);
            lval = lval * corr + lloc;
            mval = mnew;
        }
        __syncthreads();

        // ---- rescale, then P@V (2-term), term-grouped ----
        {
            float c0 = scorrf[m0 + gr], c1 = scorrf[m0 + gr + 8];
            #pragma unroll
            for (int ni = 0; ni < 8; ni++) {
                oacc[ni][0] *= c0; oacc[ni][1] *= c0;
                oacc[ni][2] *= c1; oacc[ni][3] *= c1;
            }
        }
        #pragma unroll
        for (int ks = 0; ks < 4; ks++) {
            uint32_t aoff = (uint32_t)(m0 + a_lrow) * PRB + (uint32_t)ks * 32 + a_kh;
            uint32_t Afh[4], Afl[4];
            ldsm_x4(base + OFF_PH + aoff, Afh);
            ldsm_x4(base + OFF_PL + aoff, Afl);
            uint32_t vrow = (uint32_t)(ks * 16) + a_lrow;
            uint32_t vhr[4][4];
            #pragma unroll
            for (int nj = 0; nj < 4; nj++) {
                uint32_t boff = vrow * FRB +
                    (uint32_t)(n0p + nj * 16 + ((lane >> 4) << 3)) * 2;
                ldsm_x4_t(base + OFF_VH + boff, vhr[nj]);
            }
            // term Ph*Vh
            #pragma unroll
            for (int nj = 0; nj < 4; nj++) {
                mma_f16(oacc[2*nj],   Afh, vhr[nj][0], vhr[nj][1]);
                mma_f16(oacc[2*nj+1], Afh, vhr[nj][2], vhr[nj][3]);
            }
            // term Pl*Vh
            #pragma unroll
            for (int nj = 0; nj < 4; nj++) {
                mma_f16(oacc[2*nj],   Afl, vhr[nj][0], vhr[nj][1]);
                mma_f16(oacc[2*nj+1], Afl, vhr[nj][2], vhr[nj][3]);
            }
        }
    }

    __syncthreads();
    if (q4 == 0) linvf[sr] = 1.f / lval;
    __syncthreads();

    const float i0v = linvf[m0 + gr], i1v = linvf[m0 + gr + 8];
    __half* ath = Ath + hoff;
    #pragma unroll
    for (int ni = 0; ni < 8; ni++) {
        int col = n0p + ni * 8 + tg * 2;
        *(__half2*)(ath + (size_t)(q0 + m0 + gr) * DIMN + col) =
            __floats2half2_rn(oacc[ni][0] * i0v, oacc[ni][1] * i0v);
        *(__half2*)(ath + (size_t)(q0 + m0 + gr + 8) * DIMN + col) =
            __floats2half2_rn(oacc[ni][2] * i1v, oacc[ni][3] * i1v);
    }
}

// ---------------------------------------------------------------------------
extern "C" void kernel_launch(void* const* d_in, const int* in_sizes, int n_in,
                              void* d_out, int out_size) {
    const float* x  = (const float*)d_in[0];
    const float* Wq = (const float*)d_in[1];
    const float* Wk = (const float*)d_in[2];
    const float* Wv = (const float*)d_in[3];
    const float* Wo = (const float*)d_in[4];
    float* out = (float*)d_out;

    __half *xh, *ath, *wth, *qh, *ql, *kh, *vh;
    cudaGetSymbolAddress((void**)&xh,  g_xh);
    cudaGetSymbolAddress((void**)&ath, g_ath);
    cudaGetSymbolAddress((void**)&wth, g_wth);
    cudaGetSymbolAddress((void**)&qh,  g_qh);
    cudaGetSymbolAddress((void**)&ql,  g_ql);
    cudaGetSymbolAddress((void**)&kh,  g_kh);
    cudaGetSymbolAddress((void**)&vh,  g_vh);
    const size_t WSZ = (size_t)DIMN * DIMN;

    cudaFuncSetAttribute(hgemm<0, 1>,
                         cudaFuncAttributeMaxDynamicSharedMemorySize, GSMEM);
    cudaFuncSetAttribute(hgemm<1, 1>,
                         cudaFuncAttributeMaxDynamicSharedMemorySize, GSMEM);
    cudaFuncSetAttribute(flash2,
                         cudaFuncAttributeMaxDynamicSharedMemorySize, FLASH2_SMEM);

    // idx 0-2: prep; idx 3 = fused QKV GEMM (ncu capture slot)
    cvt_rows<<<(MTOT * DIMN) / 1024, 256>>>(x, xh);
    dim3 tga(DIMN / 32, DIMN / 32, 4), tb(32, 8);
    split_transpose_all<<<tga, tb>>>(Wq, Wk, Wv, Wo, wth);
    rope_table<<<(SS * 64) / 256, 256>>>();

    dim3 gqkv(3 * DIMN / 256, MTOT / 128);   // (24, 32)
    hgemm<0, 1><<<gqkv, 512, GSMEM>>>(xh, nullptr, wth, nullptr,
                                      qh, ql, kh, vh);

    flash2<<<dim3(SS / 64, HH, BB), 256, FLASH2_SMEM>>>(qh, ql, kh, vh, ath);

    dim3 go(DIMN / 256, MTOT / 128);         // (8, 32)
    hgemm<1, 1><<<go, 512, GSMEM>>>(ath, nullptr, wth + 3 * WSZ, out,
                                    nullptr, nullptr, nullptr, nullptr);
}

// round 17
// speedup vs baseline: 1.8274x; 1.0754x over previous
#include <cuda_runtime.h>
#include <cuda_fp16.h>
#include <math_constants.h>
#include <math.h>
#include <cstdint>

#define DIMN 2048
#define BB 2
#define SS 2048
#define HH 16
#define HDD 128
#define MTOT (BB*SS)   // 4096

// ---------------------------------------------------------------------------
// Scratch (alloc-free rule: __device__ globals)
// ---------------------------------------------------------------------------
__device__ __half g_xh[(size_t)MTOT * DIMN];
__device__ __half g_ath[(size_t)MTOT * DIMN];
__device__ __half g_wth[4][(size_t)DIMN * DIMN];   // W^T hi, [N][K]
__device__ __half g_qh[(size_t)MTOT * DIMN];
__device__ __half g_kh[(size_t)MTOT * DIMN];
__device__ __half g_vh[(size_t)MTOT * DIMN];
__device__ float2 g_rope[(size_t)SS * 64];         // (cos, sin) per (s, dp)

// ---------------------------------------------------------------------------
// PTX helpers (generic sm_80+ features only)
// ---------------------------------------------------------------------------
__device__ __forceinline__ void cp_async16_s(uint32_t s, const void* g) {
    asm volatile("cp.async.cg.shared.global [%0], [%1], 16;\n" :: "r"(s), "l"(g));
}
#define CP_COMMIT() asm volatile("cp.async.commit_group;\n")

__device__ __forceinline__ uint32_t smem_u32(const void* p) {
    uint32_t a;
    asm("{ .reg .u64 t; cvta.to.shared.u64 t, %1; cvt.u32.u64 %0, t; }"
        : "=r"(a) : "l"(p));
    return a;
}

__device__ __forceinline__ void ldsm_x4(uint32_t addr, uint32_t* r) {
    asm volatile("ldmatrix.sync.aligned.m8n8.x4.shared.b16 {%0,%1,%2,%3}, [%4];"
                 : "=r"(r[0]), "=r"(r[1]), "=r"(r[2]), "=r"(r[3]) : "r"(addr));
}
__device__ __forceinline__ void ldsm_x4_t(uint32_t addr, uint32_t* r) {
    asm volatile("ldmatrix.sync.aligned.m8n8.x4.trans.shared.b16 {%0,%1,%2,%3}, [%4];"
                 : "=r"(r[0]), "=r"(r[1]), "=r"(r[2]), "=r"(r[3]) : "r"(addr));
}

__device__ __forceinline__ void mma_f16(float* d, const uint32_t* a,
                                        uint32_t b0, uint32_t b1) {
    asm volatile(
        "mma.sync.aligned.m16n8k16.row.col.f32.f16.f16.f32 "
        "{%0,%1,%2,%3}, {%4,%5,%6,%7}, {%8,%9}, {%0,%1,%2,%3};"
        : "+f"(d[0]), "+f"(d[1]), "+f"(d[2]), "+f"(d[3])
        : "r"(a[0]), "r"(a[1]), "r"(a[2]), "r"(a[3]), "r"(b0), "r"(b1));
}

// ---------------------------------------------------------------------------
// Prep: convert fp32 rows to fp16 (hi only)
// ---------------------------------------------------------------------------
__global__ void cvt_rows(const float* __restrict__ in,
                         __half* __restrict__ h) {
    size_t i = ((size_t)blockIdx.x * 256 + threadIdx.x) * 4;
    float4 v = *(const float4*)(in + i);
    *(__half2*)(h + i)     = __floats2half2_rn(v.x, v.y);
    *(__half2*)(h + i + 2) = __floats2half2_rn(v.z, v.w);
}

// ---------------------------------------------------------------------------
// Prep: transpose all 4 weights (blockIdx.z selects) -> W^T fp16 hi
// ---------------------------------------------------------------------------
__global__ void split_transpose_all(const float* __restrict__ W0,
                                    const float* __restrict__ W1,
                                    const float* __restrict__ W2,
                                    const float* __restrict__ W3,
                                    __half* __restrict__ th) {
    __shared__ float ts[32][33];
    const float* W = (blockIdx.z == 0) ? W0 : (blockIdx.z == 1) ? W1
                   : (blockIdx.z == 2) ? W2 : W3;
    const size_t mo = (size_t)blockIdx.z * DIMN * DIMN;
    const int bx = blockIdx.x * 32, by = blockIdx.y * 32;
    const int tx = threadIdx.x, ty = threadIdx.y;   // 32 x 8
    #pragma unroll
    for (int j = 0; j < 4; j++)
        ts[ty + 8 * j][tx] = W[(size_t)(by + ty + 8 * j) * DIMN + bx + tx];
    __syncthreads();
    #pragma unroll
    for (int j = 0; j < 4; j++) {
        float v = ts[tx][ty + 8 * j];
        th[mo + (size_t)(bx + ty + 8 * j) * DIMN + by + tx] = __float2half(v);
    }
}

// ---------------------------------------------------------------------------
// Prep: RoPE cos/sin table  g_rope[s][dp]
// ---------------------------------------------------------------------------
__global__ void rope_table() {
    int idx = blockIdx.x * 256 + threadIdx.x;    // 0 .. SS*64-1
    int s = idx >> 6, dp = idx & 63;
    float inv = powf(10000.0f, -(float)dp * (1.0f / 64.0f));
    float sn, cs;
    sincosf((float)s * inv, &sn, &cs);
    g_rope[idx] = make_float2(cs, sn);
}

// ---------------------------------------------------------------------------
// fp16 1-term GEMM: C = Ah@Bh^T, all operands fp16 hi.
// Block tile 128x256, BK=32, 512 threads (16 warps, warp tile 32x64),
// 3-stage cp.async, latency-spread mma ordering.
// MODE 0: QKV epilogue — RoPE via table; q,k,v -> fp16 hi.
// MODE 1: plain fp32 epilogue to C.
// ---------------------------------------------------------------------------
#define ROWB 80
#define A_BYTES (128 * ROWB)            // 10240
#define B_BYTES (256 * ROWB)            // 20480
#define STG_BYTES (A_BYTES + B_BYTES)   // 30720
#define NSTAGE 3
#define GSMEM (NSTAGE * STG_BYTES)      // 92160

__device__ __forceinline__ void fill_stage(uint32_t stg,
        const __half* ah, const __half* bh, int k0, int t) {
    {
        int row = t >> 2, cc = t & 3;
        uint32_t so = (uint32_t)(row * ROWB + cc * 16);
        size_t g = (size_t)row * DIMN + k0 + cc * 8;
        cp_async16_s(stg + so, ah + g);
    }
    #pragma unroll
    for (int i = 0; i < 2; i++) {
        int c = t + (i << 9);
        int row = c >> 2, cc = c & 3;
        uint32_t so = (uint32_t)(row * ROWB + cc * 16);
        size_t g = (size_t)row * DIMN + k0 + cc * 8;
        cp_async16_s(stg + A_BYTES + so, bh + g);
    }
}

template <int MODE>
__global__ __launch_bounds__(512)
void hgemm(const __half* __restrict__ Ah, const __half* __restrict__ Bh,
           float* __restrict__ C,
           __half* __restrict__ qh, __half* __restrict__ kh,
           __half* __restrict__ vh) {
    extern __shared__ char dsm[];
    const uint32_t base = smem_u32(dsm);

    const int t    = threadIdx.x;
    const int lane = t & 31;
    const int warp = t >> 5;              // 0..15
    const int wm   = warp & 3;            // m offset 32*wm
    const int wn   = warp >> 2;           // n offset 64*wn
    const int bm   = blockIdx.y << 7;
    const int bn   = blockIdx.x << 8;     // 256-wide tiles

    const __half* ah0 = Ah + (size_t)bm * DIMN;
    const __half* bh0 = Bh + (size_t)bn * DIMN;

    const int nloc = bn & 2047;

    float acc[2][8][4];
    #pragma unroll
    for (int mi = 0; mi < 2; mi++)
        #pragma unroll
        for (int ni = 0; ni < 8; ni++)
            #pragma unroll
            for (int e = 0; e < 4; e++) acc[mi][ni][e] = 0.f;

    const uint32_t a_lrow  = (uint32_t)(lane & 15);
    const uint32_t a_khalf = (uint32_t)(lane >> 4) * 16;

    fill_stage(base, ah0, bh0, 0, t);
    CP_COMMIT();
    fill_stage(base + STG_BYTES, ah0, bh0, 32, t);
    CP_COMMIT();

    const int NT = DIMN / 32;   // 64
    uint32_t sidx = 0, fidx = 2;
    for (int kt = 0; kt < NT; kt++) {
        if (kt + 2 < NT) {
            fill_stage(base + fidx * STG_BYTES, ah0, bh0, (kt + 2) * 32, t);
            CP_COMMIT();
            asm volatile("cp.async.wait_group 2;\n");
        } else {
            asm volatile("cp.async.wait_group 0;\n");
        }
        __syncthreads();

        const uint32_t stg  = base + sidx * STG_BYTES;
        const uint32_t As_h = stg;
        const uint32_t Bs_h = stg + A_BYTES;

        #pragma unroll
        for (int ks = 0; ks < 2; ks++) {
            const uint32_t kb = (uint32_t)ks * 32;
            uint32_t Afh[2][4];
            #pragma unroll
            for (int mi = 0; mi < 2; mi++) {
                uint32_t ro = (uint32_t)(wm * 32 + mi * 16) + a_lrow;
                uint32_t off = ro * ROWB + kb + a_khalf;
                ldsm_x4(As_h + off, Afh[mi]);
            }
            #pragma unroll
            for (int nj = 0; nj < 4; nj++) {
                uint32_t ro = (uint32_t)(wn * 64 + nj * 16) + a_lrow;
                uint32_t off = ro * ROWB + kb + a_khalf;
                uint32_t rh[4];
                ldsm_x4(Bs_h + off, rh);
                mma_f16(acc[0][2*nj],   Afh[0], rh[0], rh[2]);
                mma_f16(acc[1][2*nj],   Afh[1], rh[0], rh[2]);
                mma_f16(acc[0][2*nj+1], Afh[0], rh[1], rh[3]);
                mma_f16(acc[1][2*nj+1], Afh[1], rh[1], rh[3]);
            }
        }
        __syncthreads();

        sidx = (sidx + 1 == NSTAGE) ? 0 : sidx + 1;
        fidx = (fidx + 1 == NSTAGE) ? 0 : fidx + 1;
    }

    const int gr = lane >> 2, tg = lane & 3;
    if (MODE == 1) {
        #pragma unroll
        for (int mi = 0; mi < 2; mi++) {
            #pragma unroll
            for (int ni = 0; ni < 8; ni++) {
                const int m = bm + wm * 32 + mi * 16 + gr;
                const int n = nloc + wn * 64 + ni * 8 + tg * 2;
                *(float2*)(C + (size_t)m * DIMN + n) =
                    make_float2(acc[mi][ni][0], acc[mi][ni][1]);
                *(float2*)(C + (size_t)(m + 8) * DIMN + n) =
                    make_float2(acc[mi][ni][2], acc[mi][ni][3]);
            }
        }
    } else {
        const int gm = bn >> 11;                 // 0=q, 1=k, 2=v
        __half* dst = (gm == 0) ? qh : (gm == 1) ? kh : vh;
        const bool dorope = (gm < 2);
        #pragma unroll
        for (int mi = 0; mi < 2; mi++) {
            #pragma unroll
            for (int ni = 0; ni < 8; ni++) {
                const int n  = nloc + wn * 64 + ni * 8 + tg * 2;
                const int r0 = bm + wm * 32 + mi * 16 + gr;
                float v0 = acc[mi][ni][0], v1 = acc[mi][ni][1];
                float v2 = acc[mi][ni][2], v3 = acc[mi][ni][3];
                if (dorope) {
                    int dp = (n >> 1) & 63;
                    float2 c0 = g_rope[(size_t)(r0 & (SS - 1)) * 64 + dp];
                    float2 c1 = g_rope[(size_t)((r0 + 8) & (SS - 1)) * 64 + dp];
                    float t0 = v0 * c0.x - v1 * c0.y, t1 = v0 * c0.y + v1 * c0.x;
                    v0 = t0; v1 = t1;
                    float t2 = v2 * c1.x - v3 * c1.y, t3 = v2 * c1.y + v3 * c1.x;
                    v2 = t2; v3 = t3;
                }
                *(__half2*)(dst + (size_t)r0 * DIMN + n) =
                    __floats2half2_rn(v0, v1);
                *(__half2*)(dst + (size_t)(r0 + 8) * DIMN + n) =
                    __floats2half2_rn(v2, v3);
            }
        }
    }
}

// ---------------------------------------------------------------------------
// flash2: fp16 1-term tensor-core causal flash attention, BM=BN=64, 256 thr.
// QK: Q hi x K hi. PV: P hi x V hi. fp32 accumulate + fp32 softmax.
// Emits att as fp16 hi.
// ---------------------------------------------------------------------------
#define FRB 272                 // Q/K/V smem row bytes (128 fp16 + 16 pad)
#define PRB 144                 // P smem row bytes (64 fp16 + 16 pad)
#define SST 66                  // Ss fp32 stride
#define OFF_QH 0
#define OFF_KH 17408
#define OFF_VH 34816
#define OFF_SSX 52224
#define OFF_PH 69120
#define OFF_CORR 78336
#define OFF_LINV 78592
#define FLASH2_SMEM 78848

__global__ __launch_bounds__(256, 1)
void flash2(const __half* __restrict__ Qh, const __half* __restrict__ Kh,
            const __half* __restrict__ Vh, __half* __restrict__ Ath) {
    extern __shared__ char fsm[];
    const uint32_t base = smem_u32(fsm);
    float* Ssf    = (float*)(fsm + OFF_SSX);
    float* scorrf = (float*)(fsm + OFF_CORR);
    float* linvf  = (float*)(fsm + OFF_LINV);
    __half* Psh = (__half*)(fsm + OFF_PH);

    const int t = threadIdx.x, lane = t & 31, warp = t >> 5;
    const int qt = blockIdx.x, h = blockIdx.y, b = blockIdx.z;
    const int q0 = qt * 64;
    const float scale = 0.08838834764831845f;   // 1/sqrt(128)

    const size_t hoff = ((size_t)b * SS) * DIMN + (size_t)h * HDD;
    const __half* qhp = Qh + hoff;
    const __half* khp = Kh + hoff;
    const __half* vhp = Vh + hoff;

    #pragma unroll
    for (int i = 0; i < 4; i++) {
        int c = t + (i << 8);
        int row = c >> 4, cc = c & 15;
        uint32_t so = (uint32_t)(row * FRB + cc * 16);
        size_t g = (size_t)(q0 + row) * DIMN + cc * 8;
        cp_async16_s(base + OFF_QH + so, qhp + g);
    }
    CP_COMMIT();

    const int m0  = (warp >> 1) * 16;
    const int n0q = (warp & 1) * 32;
    const int n0p = (warp & 1) * 64;
    const int gr = lane >> 2, tg = lane & 3;
    const int sr = t >> 2, q4 = t & 3;

    const uint32_t a_lrow = (uint32_t)(lane & 15);
    const uint32_t a_kh   = (uint32_t)(lane >> 4) * 16;

    float oacc[8][4];
    #pragma unroll
    for (int ni = 0; ni < 8; ni++)
        #pragma unroll
        for (int e = 0; e < 4; e++) oacc[ni][e] = 0.f;
    float mval = -CUDART_INF_F, lval = 0.f;

    for (int kt = 0; kt <= qt; kt++) {
        const int k0 = kt * 64;
        __syncthreads();
        #pragma unroll
        for (int i = 0; i < 4; i++) {
            int c = t + (i << 8);
            int row = c >> 4, cc = c & 15;
            uint32_t so = (uint32_t)(row * FRB + cc * 16);
            size_t g = (size_t)(k0 + row) * DIMN + cc * 8;
            cp_async16_s(base + OFF_KH + so, khp + g);
            cp_async16_s(base + OFF_VH + so, vhp + g);
        }
        CP_COMMIT();
        asm volatile("cp.async.wait_group 0;\n");
        __syncthreads();

        // ---- QK^T (1-term) ----
        float sacc[4][4];
        #pragma unroll
        for (int ni = 0; ni < 4; ni++)
            #pragma unroll
            for (int e = 0; e < 4; e++) sacc[ni][e] = 0.f;
        #pragma unroll
        for (int ks = 0; ks < 8; ks++) {
            const uint32_t kb = (uint32_t)ks * 32;
            uint32_t Bfh[4][2];
            #pragma unroll
            for (int nj = 0; nj < 2; nj++) {
                uint32_t ro = (uint32_t)(n0q + nj * 16) + a_lrow;
                uint32_t off = ro * FRB + kb + a_kh;
                uint32_t rh[4];
                ldsm_x4(base + OFF_KH + off, rh);
                Bfh[2*nj][0] = rh[0]; Bfh[2*nj][1] = rh[2];
                Bfh[2*nj+1][0] = rh[1]; Bfh[2*nj+1][1] = rh[3];
            }
            uint32_t aoff = (uint32_t)(m0 + a_lrow) * FRB + kb + a_kh;
            uint32_t Afh[4];
            ldsm_x4(base + OFF_QH + aoff, Afh);
            #pragma unroll
            for (int ni = 0; ni < 4; ni++)
                mma_f16(sacc[ni], Afh, Bfh[ni][0], Bfh[ni][1]);
        }
        #pragma unroll
        for (int ni = 0; ni < 4; ni++) {
            int cn = n0q + ni * 8 + tg * 2;
            int r0 = m0 + gr, r1 = r0 + 8;
            float s0 = sacc[ni][0] * scale, s1 = sacc[ni][1] * scale;
            float s2 = sacc[ni][2] * scale, s3 = sacc[ni][3] * scale;
            if (k0 + cn     > q0 + r0) s0 = -CUDART_INF_F;
            if (k0 + cn + 1 > q0 + r0) s1 = -CUDART_INF_F;
            if (k0 + cn     > q0 + r1) s2 = -CUDART_INF_F;
            if (k0 + cn + 1 > q0 + r1) s3 = -CUDART_INF_F;
            Ssf[r0 * SST + cn]     = s0;
            Ssf[r0 * SST + cn + 1] = s1;
            Ssf[r1 * SST + cn]     = s2;
            Ssf[r1 * SST + cn + 1] = s3;
        }
        __syncthreads();

        // ---- online softmax (quad per row), emit P fp16 hi ----
        {
            float* srow = Ssf + sr * SST + q4 * 16;
            float mloc = -CUDART_INF_F;
            #pragma unroll
            for (int j = 0; j < 16; j++) mloc = fmaxf(mloc, srow[j]);
            mloc = fmaxf(mloc, __shfl_xor_sync(0xFFFFFFFFu, mloc, 1));
            mloc = fmaxf(mloc, __shfl_xor_sync(0xFFFFFFFFu, mloc, 2));
            float mnew = fmaxf(mval, mloc);
            float corr = __expf(mval - mnew);
            if (q4 == 0) scorrf[sr] = corr;
            __half* php = Psh + sr * (PRB / 2) + q4 * 16;
            float lloc = 0.f;
            #pragma unroll
            for (int j = 0; j < 16; j++) {
                float p = __expf(srow[j] - mnew);
                php[j] = __float2half(p);
                lloc += p;
            }
            lloc += __shfl_xor_sync(0xFFFFFFFFu, lloc, 1);
            lloc += __shfl_xor_sync(0xFFFFFFFFu, lloc, 2);
            lval = lval * corr + lloc;
            mval = mnew;
        }
        __syncthreads();

        // ---- rescale, then P@V (1-term) ----
        {
            float c0 = scorrf[m0 + gr], c1 = scorrf[m0 + gr + 8];
            #pragma unroll
            for (int ni = 0; ni < 8; ni++) {
                oacc[ni][0] *= c0; oacc[ni][1] *= c0;
                oacc[ni][2] *= c1; oacc[ni][3] *= c1;
            }
        }
        #pragma unroll
        for (int ks = 0; ks < 4; ks++) {
            uint32_t aoff = (uint32_t)(m0 + a_lrow) * PRB + (uint32_t)ks * 32 + a_kh;
            uint32_t Afh[4];
            ldsm_x4(base + OFF_PH + aoff, Afh);
            uint32_t vrow = (uint32_t)(ks * 16) + a_lrow;
            #pragma unroll
            for (int nj = 0; nj < 4; nj++) {
                uint32_t boff = vrow * FRB +
                    (uint32_t)(n0p + nj * 16 + ((lane >> 4) << 3)) * 2;
                uint32_t vhr[4];
                ldsm_x4_t(base + OFF_VH + boff, vhr);
                mma_f16(oacc[2*nj],   Afh, vhr[0], vhr[1]);
                mma_f16(oacc[2*nj+1], Afh, vhr[2], vhr[3]);
            }
        }
    }

    __syncthreads();
    if (q4 == 0) linvf[sr] = 1.f / lval;
    __syncthreads();

    const float i0v = linvf[m0 + gr], i1v = linvf[m0 + gr + 8];
    __half* ath = Ath + hoff;
    #pragma unroll
    for (int ni = 0; ni < 8; ni++) {
        int col = n0p + ni * 8 + tg * 2;
        *(__half2*)(ath + (size_t)(q0 + m0 + gr) * DIMN + col) =
            __floats2half2_rn(oacc[ni][0] * i0v, oacc[ni][1] * i0v);
        *(__half2*)(ath + (size_t)(q0 + m0 + gr + 8) * DIMN + col) =
            __floats2half2_rn(oacc[ni][2] * i1v, oacc[ni][3] * i1v);
    }
}

// ---------------------------------------------------------------------------
extern "C" void kernel_launch(void* const* d_in, const int* in_sizes, int n_in,
                              void* d_out, int out_size) {
    const float* x  = (const float*)d_in[0];
    const float* Wq = (const float*)d_in[1];
    const float* Wk = (const float*)d_in[2];
    const float* Wv = (const float*)d_in[3];
    const float* Wo = (const float*)d_in[4];
    float* out = (float*)d_out;

    __half *xh, *ath, *wth, *qh, *kh, *vh;
    cudaGetSymbolAddress((void**)&xh,  g_xh);
    cudaGetSymbolAddress((void**)&ath, g_ath);
    cudaGetSymbolAddress((void**)&wth, g_wth);
    cudaGetSymbolAddress((void**)&qh,  g_qh);
    cudaGetSymbolAddress((void**)&kh,  g_kh);
    cudaGetSymbolAddress((void**)&vh,  g_vh);
    const size_t WSZ = (size_t)DIMN * DIMN;

    cudaFuncSetAttribute(hgemm<0>,
                         cudaFuncAttributeMaxDynamicSharedMemorySize, GSMEM);
    cudaFuncSetAttribute(hgemm<1>,
                         cudaFuncAttributeMaxDynamicSharedMemorySize, GSMEM);
    cudaFuncSetAttribute(flash2,
                         cudaFuncAttributeMaxDynamicSharedMemorySize, FLASH2_SMEM);

    // idx 0-2: prep; idx 3 = fused QKV GEMM (ncu capture slot)
    cvt_rows<<<(MTOT * DIMN) / 1024, 256>>>(x, xh);
    dim3 tga(DIMN / 32, DIMN / 32, 4), tb(32, 8);
    split_transpose_all<<<tga, tb>>>(Wq, Wk, Wv, Wo, wth);
    rope_table<<<(SS * 64) / 256, 256>>>();

    dim3 gqkv(3 * DIMN / 256, MTOT / 128);   // (24, 32)
    hgemm<0><<<gqkv, 512, GSMEM>>>(xh, wth, nullptr, qh, kh, vh);

    flash2<<<dim3(SS / 64, HH, BB), 256, FLASH2_SMEM>>>(qh, kh, vh, ath);

    dim3 go(DIMN / 256, MTOT / 128);         // (8, 32)
    hgemm<1><<<go, 512, GSMEM>>>(ath, wth + 3 * WSZ, out,
                                 nullptr, nullptr, nullptr);
}